// round 14
// baseline (speedup 1.0000x reference)
#include <cuda_runtime.h>
#include <cuda_bf16.h>
#include <math.h>
#include <stdint.h>

#define BSZ   8
#define DIM   512
#define NTOK  1024
#define EMBD  128
#define CDIM  512
#define MTOK  256
#define HEADS 8
#define DHEAD 64
#define INNER 512
#define DFF   2048
#define GROUPS 32

// ---------------- scratch (device globals; no allocations allowed) ----------
__device__ float g_xt [BSZ*NTOK*DIM];
__device__ float g_buf[BSZ*NTOK*DIM];
__device__ __nv_bfloat16 g_bbuf[BSZ*NTOK*DIM];
__device__ __nv_bfloat16 g_qkvh[BSZ*NTOK*3*INNER];
__device__ __nv_bfloat16 g_qh [BSZ*NTOK*INNER];
__device__ __nv_bfloat16 g_kvh2[BSZ*MTOK*2*INNER];
__device__ __nv_bfloat16 g_oh [BSZ*NTOK*INNER];
__device__ __nv_bfloat16 g_vfh[BSZ*NTOK*DFF];
__device__ __nv_bfloat16 g_ctxT[BSZ*MTOK*CDIM];
__device__ __nv_bfloat16 g_wconv[DIM*DIM];
__device__ __nv_bfloat16 g_wqkv[3*INNER*DIM];
__device__ __nv_bfloat16 g_w1o[DIM*INNER];
__device__ __nv_bfloat16 g_w2q[INNER*DIM];
__device__ __nv_bfloat16 g_wkv2[2*INNER*CDIM];
__device__ __nv_bfloat16 g_w2o[DIM*INNER];
__device__ __nv_bfloat16 g_wf1p[2*DFF*DIM];
__device__ __nv_bfloat16 g_wf2[DIM*DFF];
__device__ float g_pb1[2*DFF];
__device__ float g_scale[BSZ*DIM];
__device__ float g_shift[BSZ*DIM];
__device__ float g_gn_mu[BSZ*GROUPS];
__device__ float g_gn_rs[BSZ*GROUPS];

// ---------------- helpers ----------------------------------------------------
__device__ __forceinline__ float block_reduce_sum(float v, float* sh) {
    __syncthreads();
    #pragma unroll
    for (int o = 16; o > 0; o >>= 1) v += __shfl_xor_sync(0xffffffffu, v, o);
    int warp = threadIdx.x >> 5;
    if ((threadIdx.x & 31) == 0) sh[warp] = v;
    __syncthreads();
    int nw = blockDim.x >> 5;
    v = (threadIdx.x < nw) ? sh[threadIdx.x] : 0.f;
    if (threadIdx.x < 32) {
        #pragma unroll
        for (int o = 16; o > 0; o >>= 1) v += __shfl_xor_sync(0xffffffffu, v, o);
    }
    if (threadIdx.x == 0) sh[0] = v;
    __syncthreads();
    return sh[0];
}

__device__ __forceinline__ void mma16816(float* c, const uint32_t* a, const uint32_t* b) {
    asm volatile(
        "mma.sync.aligned.m16n8k16.row.col.f32.bf16.bf16.f32 "
        "{%0,%1,%2,%3}, {%4,%5,%6,%7}, {%8,%9}, {%0,%1,%2,%3};\n"
        : "+f"(c[0]), "+f"(c[1]), "+f"(c[2]), "+f"(c[3])
        : "r"(a[0]), "r"(a[1]), "r"(a[2]), "r"(a[3]), "r"(b[0]), "r"(b[1]));
}

__device__ __forceinline__ void ldsm4(uint32_t* r, uint32_t a) {
    asm volatile("ldmatrix.sync.aligned.m8n8.x4.shared.b16 {%0,%1,%2,%3}, [%4];\n"
        : "=r"(r[0]), "=r"(r[1]), "=r"(r[2]), "=r"(r[3]) : "r"(a));
}
__device__ __forceinline__ void ldsm4t(uint32_t* r, uint32_t a) {
    asm volatile("ldmatrix.sync.aligned.m8n8.x4.trans.shared.b16 {%0,%1,%2,%3}, [%4];\n"
        : "=r"(r[0]), "=r"(r[1]), "=r"(r[2]), "=r"(r[3]) : "r"(a));
}

__device__ __forceinline__ void cpa16(uint32_t s, const void* g) {
    asm volatile("cp.async.ca.shared.global [%0], [%1], 16;\n" :: "r"(s), "l"(g));
}
__device__ __forceinline__ void cpa_commit() { asm volatile("cp.async.commit_group;\n"); }
__device__ __forceinline__ void cpa_wait0()  { asm volatile("cp.async.wait_group 0;\n" ::: "memory"); }
__device__ __forceinline__ void cpa_wait1()  { asm volatile("cp.async.wait_group 1;\n" ::: "memory"); }

__device__ __forceinline__ float gelu_exact(float g) {
    return 0.5f * g * (1.f + erff(g * 0.70710678118654752f));
}

// ---------------- bf16 GEMM (OUT_MODE compile-time) ---------------------------
// OUT_MODE: 0 fp32 (+bias +Res), 1 bf16 (+bias), 2 geglu-bf16, 3 fp32-transposed
template<int BM, int BN, int WM, int WN, int OUT_MODE>
__global__ __launch_bounds__(256) void gemm_bb(
    const __nv_bfloat16* __restrict__ A, int lda,
    const __nv_bfloat16* __restrict__ Bm, int ldb,
    void* __restrict__ Cv, int ldc,
    const float* __restrict__ bias,
    const float* __restrict__ Res, int ldr,
    int K, float alpha)
{
    constexpr int BK = 32, AP = 40;
    constexpr int WARPS_N = BN / WN;
    constexpr int MT = WM / 16, NT = WN / 8;
    constexpr int ACH = BM * 4 / 256;
    constexpr int BCH = BN * 4 / 256;

    int i0 = blockIdx.y * BM, j0 = blockIdx.x * BN;
    __shared__ __align__(16) __nv_bfloat16 As[2][BM][AP];
    __shared__ __align__(16) __nv_bfloat16 Bs[2][BN][AP];
    uint32_t sA0 = (uint32_t)__cvta_generic_to_shared(&As[0][0][0]);
    uint32_t sB0 = (uint32_t)__cvta_generic_to_shared(&Bs[0][0][0]);

    int tid = threadIdx.x, warp = tid >> 5, lane = tid & 31;
    int g = lane >> 2, tg = lane & 3;
    int m_w = (warp / WARPS_N) * WM, n_w = (warp % WARPS_N) * WN;

    uint32_t aBase = sA0 + (uint32_t)(((m_w + (lane & 15)) * AP + ((lane >> 4) * 8)) * 2);
    uint32_t bBase = sB0 + (uint32_t)(((n_w + ((lane & 7) | ((lane & 16) >> 1))) * AP + (lane & 8)) * 2);

    float acc[MT][NT][4] = {};

    auto load_tiles = [&](int k0, int buf) {
        #pragma unroll
        for (int t = 0; t < ACH; t++) {
            int c = tid + t * 256;
            int row = c >> 2, off = (c & 3) * 8;
            cpa16(sA0 + buf * (BM * AP * 2) + (row * AP + off) * 2,
                  A + (long)(i0 + row) * lda + k0 + off);
        }
        #pragma unroll
        for (int t = 0; t < BCH; t++) {
            int c = tid + t * 256;
            int row = c >> 2, off = (c & 3) * 8;
            cpa16(sB0 + buf * (BN * AP * 2) + (row * AP + off) * 2,
                  Bm + (long)(j0 + row) * ldb + k0 + off);
        }
        cpa_commit();
    };

    load_tiles(0, 0);
    cpa_wait0();
    __syncthreads();

    int KB = K / BK;
    for (int kb = 0; kb < KB; kb++) {
        int cur = kb & 1;
        if (kb + 1 < KB) load_tiles((kb + 1) * BK, cur ^ 1);
        uint32_t aB = aBase + cur * (BM * AP * 2);
        uint32_t bB = bBase + cur * (BN * AP * 2);
        uint32_t af[2][MT][4];
        uint32_t bf[2][NT][2];
        #pragma unroll
        for (int ks2 = 0; ks2 < 2; ks2++) {
            #pragma unroll
            for (int mt = 0; mt < MT; mt++)
                ldsm4(af[ks2][mt], aB + (mt * 16 * AP + ks2 * 16) * 2);
            #pragma unroll
            for (int p = 0; p < NT / 2; p++) {
                uint32_t r[4];
                ldsm4(r, bB + (p * 16 * AP + ks2 * 16) * 2);
                bf[ks2][2*p][0] = r[0]; bf[ks2][2*p][1] = r[1];
                bf[ks2][2*p+1][0] = r[2]; bf[ks2][2*p+1][1] = r[3];
            }
        }
        #pragma unroll
        for (int ks2 = 0; ks2 < 2; ks2++)
            #pragma unroll
            for (int mt = 0; mt < MT; mt++)
                #pragma unroll
                for (int nt = 0; nt < NT; nt++)
                    mma16816(acc[mt][nt], af[ks2][mt], bf[ks2][nt]);
        if (kb + 1 < KB) cpa_wait0();
        __syncthreads();
    }

    float* Cf = reinterpret_cast<float*>(Cv);
    __nv_bfloat16* Ch = reinterpret_cast<__nv_bfloat16*>(Cv);

    if (OUT_MODE == 3) {
        constexpr int SP = 33;
        float* stage = reinterpret_cast<float*>(&As[0][0][0]);
        int bb = i0 >> 10;
        int nbase = i0 & (NTOK - 1);
        #pragma unroll
        for (int pass = 0; pass < 4; pass++) {
            __syncthreads();
            int rlo = pass * 32;
            #pragma unroll
            for (int mt = 0; mt < MT; mt++) {
                #pragma unroll
                for (int h = 0; h < 2; h++) {
                    int il = m_w + mt*16 + g + 8*h;
                    if (il >= rlo && il < rlo + 32) {
                        #pragma unroll
                        for (int nt = 0; nt < NT; nt++) {
                            int j = n_w + nt*8 + tg*2;
                            float v0 = alpha * acc[mt][nt][2*h]   + bias[j0 + j];
                            float v1 = alpha * acc[mt][nt][2*h+1] + bias[j0 + j + 1];
                            const float* rp = &Res[(long)(i0 + il) * ldr + j0 + j];
                            v0 += rp[0]; v1 += rp[1];
                            stage[j * SP + (il & 31)]       = v0;
                            stage[(j + 1) * SP + (il & 31)] = v1;
                        }
                    }
                }
            }
            __syncthreads();
            for (int q = tid; q < BN * 2; q += 256) {
                int c = q >> 1, half = q & 1;
                float* op = &Cf[((long)bb * DIM + j0 + c) * NTOK + nbase + rlo + half*16];
                float* sp = &stage[c * SP + half * 16];
                #pragma unroll
                for (int s = 0; s < 4; s++) {
                    ((float4*)op)[s] = make_float4(sp[s*4], sp[s*4+1], sp[s*4+2], sp[s*4+3]);
                }
            }
        }
        return;
    }

    #pragma unroll
    for (int mt = 0; mt < MT; mt++) {
        #pragma unroll
        for (int h = 0; h < 2; h++) {
            int i = i0 + m_w + mt*16 + g + 8*h;
            #pragma unroll
            for (int nt = 0; nt < NT; nt++) {
                int j = j0 + n_w + nt*8 + tg*2;
                float v0 = alpha * acc[mt][nt][2*h+0];
                float v1 = alpha * acc[mt][nt][2*h+1];
                if (bias) { v0 += bias[j]; v1 += bias[j+1]; }
                if (OUT_MODE == 2) {
                    Ch[(long)i * ldc + (j >> 1)] = __float2bfloat16_rn(v0 * gelu_exact(v1));
                } else if (OUT_MODE == 1) {
                    *reinterpret_cast<__nv_bfloat162*>(&Ch[(long)i * ldc + j]) =
                        __floats2bfloat162_rn(v0, v1);
                } else {
                    if (Res) {
                        const float* rp = &Res[(long)i * ldr + j];
                        v0 += rp[0]; v1 += rp[1];
                    }
                    *reinterpret_cast<float2*>(&Cf[(long)i * ldc + j]) = make_float2(v0, v1);
                }
            }
        }
    }
}

// ---------------- fused flash attention (cp.async K/V pipeline) ---------------
#define FPITCH 72
#define FTILEB (64 * FPITCH * 2)
__global__ __launch_bounds__(128) void flash_kernel(
    const __nv_bfloat16* __restrict__ Q, int q_ld,
    const __nv_bfloat16* __restrict__ K,
    const __nv_bfloat16* __restrict__ V, int kv_ld,
    __nv_bfloat16* __restrict__ O,
    int nk, long kv_bstride)
{
    __shared__ __align__(16) __nv_bfloat16 Qs[64][FPITCH];
    __shared__ __align__(16) __nv_bfloat16 Ks[2][64][FPITCH];
    __shared__ __align__(16) __nv_bfloat16 Vs[2][64][FPITCH];
    uint32_t sQ = (uint32_t)__cvta_generic_to_shared(&Qs[0][0]);
    uint32_t sK = (uint32_t)__cvta_generic_to_shared(&Ks[0][0][0]);
    uint32_t sV = (uint32_t)__cvta_generic_to_shared(&Vs[0][0][0]);

    int tid = threadIdx.x, warp = tid >> 5, lane = tid & 31;
    int g = lane >> 2, tg = lane & 3;
    int b = blockIdx.y / HEADS, h = blockIdx.y % HEADS;
    const __nv_bfloat16* qb = Q + ((long)b*NTOK + blockIdx.x*64)*q_ld + h*DHEAD;
    const __nv_bfloat16* kb = K + (long)b*kv_bstride + h*DHEAD;
    const __nv_bfloat16* vb = V + (long)b*kv_bstride + h*DHEAD;
    __nv_bfloat16* ob = O + ((long)b*NTOK + blockIdx.x*64)*INNER + h*DHEAD;

    int mrow = warp * 16;
    uint32_t qBase = sQ + (uint32_t)(((mrow + (lane & 15)) * FPITCH + (lane >> 4) * 8) * 2);
    uint32_t kBase = sK + (uint32_t)((((lane & 7) | ((lane & 16) >> 1)) * FPITCH + (lane & 8)) * 2);
    uint32_t vBase = sV + (uint32_t)(((((lane >> 3) & 1) * 8 + (lane & 7)) * FPITCH + (lane >> 4) * 8) * 2);

    auto pf = [&](int kt, int buf) {
        #pragma unroll
        for (int t = 0; t < 4; t++) {
            int c = tid + t*128;
            int r = c >> 3, c8 = (c & 7) * 8;
            cpa16(sK + buf*FTILEB + (r*FPITCH + c8)*2, kb + (long)(kt + r)*kv_ld + c8);
            cpa16(sV + buf*FTILEB + (r*FPITCH + c8)*2, vb + (long)(kt + r)*kv_ld + c8);
        }
        cpa_commit();
    };

    #pragma unroll
    for (int t = 0; t < 4; t++) {
        int c = tid + t*128;
        int r = c >> 3, c8 = (c & 7) * 8;
        *reinterpret_cast<uint4*>(&Qs[r][c8]) =
            *reinterpret_cast<const uint4*>(&qb[(long)r*q_ld + c8]);
    }
    pf(0, 0);
    if (nk > 64) pf(64, 1);

    float m_i[2] = {-1e30f, -1e30f}, l_i[2] = {0.f, 0.f};
    float oa[8][4];
    #pragma unroll
    for (int nt = 0; nt < 8; nt++) { oa[nt][0]=0.f; oa[nt][1]=0.f; oa[nt][2]=0.f; oa[nt][3]=0.f; }

    __syncthreads();

    uint32_t qf[4][4];
    #pragma unroll
    for (int kc = 0; kc < 4; kc++)
        ldsm4(qf[kc], qBase + kc * 16 * 2);

    int T = nk >> 6;
    for (int t = 0; t < T; t++) {
        int buf = t & 1;
        if (t + 1 < T) cpa_wait1(); else cpa_wait0();
        __syncthreads();
        uint32_t kB = kBase + buf*FTILEB;
        uint32_t vB = vBase + buf*FTILEB;

        float s[8][4] = {};
        #pragma unroll
        for (int kc = 0; kc < 4; kc++) {
            uint32_t bk[8][2];
            #pragma unroll
            for (int p = 0; p < 4; p++) {
                uint32_t r[4];
                ldsm4(r, kB + (p * 16 * FPITCH + kc * 16) * 2);
                bk[2*p][0] = r[0]; bk[2*p][1] = r[1];
                bk[2*p+1][0] = r[2]; bk[2*p+1][1] = r[3];
            }
            #pragma unroll
            for (int nt = 0; nt < 8; nt++)
                mma16816(s[nt], qf[kc], bk[nt]);
        }

        #pragma unroll
        for (int h2 = 0; h2 < 2; h2++) {
            float mt = -1e30f;
            #pragma unroll
            for (int nt = 0; nt < 8; nt++)
                mt = fmaxf(mt, fmaxf(s[nt][2*h2], s[nt][2*h2+1]));
            mt = fmaxf(mt, __shfl_xor_sync(0xffffffffu, mt, 1));
            mt = fmaxf(mt, __shfl_xor_sync(0xffffffffu, mt, 2));
            float mnew = fmaxf(m_i[h2], mt);
            float corr = __expf(m_i[h2] - mnew);
            m_i[h2] = mnew;
            float lsum = 0.f;
            #pragma unroll
            for (int nt = 0; nt < 8; nt++) {
                float e0 = __expf(s[nt][2*h2]   - mnew);
                float e1 = __expf(s[nt][2*h2+1] - mnew);
                s[nt][2*h2] = e0; s[nt][2*h2+1] = e1;
                lsum += e0 + e1;
            }
            lsum += __shfl_xor_sync(0xffffffffu, lsum, 1);
            lsum += __shfl_xor_sync(0xffffffffu, lsum, 2);
            l_i[h2] = l_i[h2] * corr + lsum;
            #pragma unroll
            for (int nt = 0; nt < 8; nt++) { oa[nt][2*h2] *= corr; oa[nt][2*h2+1] *= corr; }
        }

        #pragma unroll
        for (int kc = 0; kc < 4; kc++) {
            uint32_t ap[4];
            __nv_bfloat162 t0 = __floats2bfloat162_rn(s[2*kc][0],   s[2*kc][1]);
            __nv_bfloat162 t1 = __floats2bfloat162_rn(s[2*kc][2],   s[2*kc][3]);
            __nv_bfloat162 t2 = __floats2bfloat162_rn(s[2*kc+1][0], s[2*kc+1][1]);
            __nv_bfloat162 t3 = __floats2bfloat162_rn(s[2*kc+1][2], s[2*kc+1][3]);
            ap[0] = *reinterpret_cast<uint32_t*>(&t0);
            ap[1] = *reinterpret_cast<uint32_t*>(&t1);
            ap[2] = *reinterpret_cast<uint32_t*>(&t2);
            ap[3] = *reinterpret_cast<uint32_t*>(&t3);
            uint32_t bv[8][2];
            #pragma unroll
            for (int p = 0; p < 4; p++) {
                uint32_t r[4];
                ldsm4t(r, vB + (kc * 16 * FPITCH + p * 16) * 2);
                bv[2*p][0] = r[0]; bv[2*p][1] = r[1];
                bv[2*p+1][0] = r[2]; bv[2*p+1][1] = r[3];
            }
            #pragma unroll
            for (int nt = 0; nt < 8; nt++)
                mma16816(oa[nt], ap, bv[nt]);
        }
        __syncthreads();
        if (t + 2 < T) pf((t + 2) * 64, buf);
    }

    #pragma unroll
    for (int h2 = 0; h2 < 2; h2++) {
        float inv = 1.f / l_i[h2];
        int r = mrow + g + 8*h2;
        #pragma unroll
        for (int nt = 0; nt < 8; nt++) {
            *reinterpret_cast<__nv_bfloat162*>(&ob[(long)r*INNER + nt*8 + tg*2]) =
                __floats2bfloat162_rn(oa[nt][2*h2] * inv, oa[nt][2*h2+1] * inv);
        }
    }
}

// ---------------- fused weight conversion -------------------------------------
#define SQW (INNER*DIM)
#define N_CONV  (DIM*DIM)
#define N_WF1   (2*DFF*DIM)
#define N_WF2   (DIM*DFF)
#define TOT_W   (N_CONV + 3*SQW + SQW + SQW + 2*SQW + SQW + N_WF1 + N_WF2)
__global__ void convert_all_kernel(
    const float* __restrict__ conv_w,
    const float* __restrict__ a1q, const float* __restrict__ a1k,
    const float* __restrict__ a1v, const float* __restrict__ a1o,
    const float* __restrict__ a2q, const float* __restrict__ a2k,
    const float* __restrict__ a2v, const float* __restrict__ a2o,
    const float* __restrict__ f1,  const float* __restrict__ f2,
    const float* __restrict__ b1)
{
    long i = (long)(blockIdx.x * 256 + threadIdx.x) * 4;
    auto cvt = [](const float* s, __nv_bfloat16* d, long si, long di, float sc) {
        float4 v = *reinterpret_cast<const float4*>(s + si);
        *reinterpret_cast<__nv_bfloat162*>(d + di)     = __floats2bfloat162_rn(v.x*sc, v.y*sc);
        *reinterpret_cast<__nv_bfloat162*>(d + di + 2) = __floats2bfloat162_rn(v.z*sc, v.w*sc);
    };
    if (i < N_CONV) { cvt(conv_w, g_wconv, i, i, 1.f); return; }
    i -= N_CONV;
    if (i < SQW)    { cvt(a1q, g_wqkv, i, i, 0.125f); return; }
    i -= SQW;
    if (i < SQW)    { cvt(a1k, g_wqkv, i, i + SQW, 1.f); return; }
    i -= SQW;
    if (i < SQW)    { cvt(a1v, g_wqkv, i, i + 2*SQW, 1.f); return; }
    i -= SQW;
    if (i < SQW)    { cvt(a1o, g_w1o, i, i, 1.f); return; }
    i -= SQW;
    if (i < SQW)    { cvt(a2q, g_w2q, i, i, 0.125f); return; }
    i -= SQW;
    if (i < SQW)    { cvt(a2k, g_wkv2, i, i, 1.f); return; }
    i -= SQW;
    if (i < SQW)    { cvt(a2v, g_wkv2, i, i + SQW, 1.f); return; }
    i -= SQW;
    if (i < SQW)    { cvt(a2o, g_w2o, i, i, 1.f); return; }
    i -= SQW;
    if (i < N_WF1) {
        int row = (int)(i / DIM), col = (int)(i % DIM);
        int srow = (row >> 1) + (row & 1) * DFF;
        cvt(f1, g_wf1p, (long)srow * DIM + col, i, 1.f);
        return;
    }
    i -= N_WF1;
    if (i < N_WF2)  { cvt(f2, g_wf2, i, i, 1.f); return; }
    i -= N_WF2;
    if (i < 2*DFF) {
        #pragma unroll
        for (int s = 0; s < 4; s++) {
            long o = i + s;
            g_pb1[o] = b1[(o >> 1) + (o & 1) * DFF];
        }
    }
}

// ---------------- small kernels ----------------------------------------------
// emb: warp-per-output, coalesced float4 row reads + warp reduce.
// grid = (BSZ * 16) blocks, 256 threads; each warp does 8 outputs.
__global__ __launch_bounds__(256) void emb_kernel(
    const float* __restrict__ emb,
    const float* __restrict__ w,
    const float* __restrict__ bias)
{
    int b = blockIdx.x >> 4, chunk = blockIdx.x & 15;
    __shared__ float e[EMBD];
    int tid = threadIdx.x, warp = tid >> 5, lane = tid & 31;
    if (tid < EMBD) {
        float v = emb[b * EMBD + tid];
        e[tid] = v / (1.f + __expf(-v));
    }
    __syncthreads();
    float4 ev = reinterpret_cast<const float4*>(e)[lane];
    #pragma unroll
    for (int q = 0; q < 8; q++) {
        int o = chunk * 64 + warp * 8 + q;     // 0..1023
        float4 wv = reinterpret_cast<const float4*>(w + (long)o * EMBD)[lane];
        float p = wv.x*ev.x + wv.y*ev.y + wv.z*ev.z + wv.w*ev.w;
        #pragma unroll
        for (int s = 16; s > 0; s >>= 1) p += __shfl_xor_sync(0xffffffffu, p, s);
        if (lane == 0) {
            float acc = p + bias[o];
            if (o < DIM) g_scale[b * DIM + o] = 1.f + acc;
            else         g_shift[b * DIM + (o - DIM)] = acc;
        }
    }
}

__global__ void gn_stats_kernel(const float* __restrict__ X)
{
    __shared__ float sh[32];
    int b = blockIdx.x / GROUPS, g = blockIdx.x % GROUPS;
    const int CH = DIM / GROUPS;
    const float* p = X + ((long)b * DIM + (long)g * CH) * NTOK;
    float s = 0.f, ss = 0.f;
    for (int i = threadIdx.x; i < CH * NTOK / 4; i += blockDim.x) {
        float4 v = reinterpret_cast<const float4*>(p)[i];
        s  += v.x + v.y + v.z + v.w;
        ss += v.x*v.x + v.y*v.y + v.z*v.z + v.w*v.w;
    }
    s  = block_reduce_sum(s, sh);
    ss = block_reduce_sum(ss, sh);
    if (threadIdx.x == 0) {
        float inv = 1.f / (CH * NTOK);
        float mu = s * inv;
        float var = ss * inv - mu * mu;
        g_gn_mu[blockIdx.x] = mu;
        g_gn_rs[blockIdx.x] = rsqrtf(var + 1e-6f);
    }
}

__global__ void gn_apply_t_kernel(const float* __restrict__ X,
                                  const float* __restrict__ gn_g,
                                  const float* __restrict__ gn_b,
                                  __nv_bfloat16* __restrict__ HT,
                                  float* __restrict__ XT)
{
    __shared__ float tile[32][33];
    int b = blockIdx.z;
    int n0 = blockIdx.x * 32, c0 = blockIdx.y * 32;
    for (int r = threadIdx.y; r < 32; r += 8)
        tile[r][threadIdx.x] = X[((long)b * DIM + c0 + r) * NTOK + n0 + threadIdx.x];
    __syncthreads();
    int c = c0 + threadIdx.x;
    int grp = b * GROUPS + (c >> 4);
    float mu = g_gn_mu[grp], rs = g_gn_rs[grp];
    float gg = gn_g[c], bb = gn_b[c];
    float sc = g_scale[b * DIM + c], sf = g_shift[b * DIM + c];
    for (int r = threadIdx.y; r < 32; r += 8) {
        int n = n0 + r;
        float raw = tile[threadIdx.x][r];
        float v = (raw - mu) * rs * gg + bb;
        v = v * sc + sf;
        float s = v / (1.f + __expf(-v));
        HT[((long)b * NTOK + n) * DIM + c] = __float2bfloat16_rn(s);
        XT[((long)b * NTOK + n) * DIM + c] = raw;
    }
}

__global__ void ctx_transpose_kernel(const float* __restrict__ CTX,
                                     __nv_bfloat16* __restrict__ CT)
{
    __shared__ float tile[32][33];
    int b = blockIdx.z;
    int m0 = blockIdx.x * 32, c0 = blockIdx.y * 32;
    for (int r = threadIdx.y; r < 32; r += 8)
        tile[r][threadIdx.x] = CTX[((long)b * CDIM + c0 + r) * MTOK + m0 + threadIdx.x];
    __syncthreads();
    for (int r = threadIdx.y; r < 32; r += 8)
        CT[((long)b * MTOK + m0 + r) * CDIM + c0 + threadIdx.x] =
            __float2bfloat16_rn(tile[threadIdx.x][r]);
}

__global__ void layernorm_kernel(const float* __restrict__ X, __nv_bfloat16* __restrict__ Y,
                                 const float* __restrict__ g, const float* __restrict__ b)
{
    __shared__ float sh[32];
    long t = blockIdx.x;
    const float* x = X + t * DIM;
    __nv_bfloat16* y = Y + t * DIM;
    float s = 0.f, ss = 0.f;
    for (int i = threadIdx.x; i < DIM; i += blockDim.x) {
        float v = x[i]; s += v; ss += v * v;
    }
    s  = block_reduce_sum(s, sh);
    ss = block_reduce_sum(ss, sh);
    float mu = s * (1.f / DIM);
    float var = ss * (1.f / DIM) - mu * mu;
    float rs = rsqrtf(var + 1e-5f);
    for (int i = threadIdx.x; i < DIM; i += blockDim.x)
        y[i] = __float2bfloat16_rn((x[i] - mu) * rs * g[i] + b[i]);
}

// ---------------- host orchestration ----------------------------------------
template<int OUT_MODE>
static void launch_bb(cudaStream_t st,
                      const __nv_bfloat16* A, int lda, const __nv_bfloat16* B, int ldb,
                      void* C, int ldc, const float* bias, const float* R, int ldr,
                      int M, int N, int K, float alpha)
{
    dim3 grid(N / 128, M / 128);
    gemm_bb<128,128,64,32,OUT_MODE><<<grid, 256, 0, st>>>(A, lda, B, ldb, C, ldc,
                                                          bias, R, ldr, K, alpha);
}

extern "C" void kernel_launch(void* const* d_in, const int* in_sizes, int n_in,
                              void* d_out, int out_size)
{
    const float* x      = (const float*)d_in[0];
    const float* emb    = (const float*)d_in[1];
    const float* ctx    = (const float*)d_in[2];
    const float* w_emb  = (const float*)d_in[3];
    const float* b_emb  = (const float*)d_in[4];
    const float* gn_g   = (const float*)d_in[5];
    const float* gn_b   = (const float*)d_in[6];
    const float* conv_w = (const float*)d_in[7];
    const float* conv_b = (const float*)d_in[8];
    const float* a1_wq  = (const float*)d_in[9];
    const float* a1_wk  = (const float*)d_in[10];
    const float* a1_wv  = (const float*)d_in[11];
    const float* a1_wo  = (const float*)d_in[12];
    const float* a1_bo  = (const float*)d_in[13];
    const float* a2_wq  = (const float*)d_in[14];
    const float* a2_wk  = (const float*)d_in[15];
    const float* a2_wv  = (const float*)d_in[16];
    const float* a2_wo  = (const float*)d_in[17];
    const float* a2_bo  = (const float*)d_in[18];
    const float* ln1_g  = (const float*)d_in[19];
    const float* ln1_b  = (const float*)d_in[20];
    const float* ln2_g  = (const float*)d_in[21];
    const float* ln2_b  = (const float*)d_in[22];
    const float* ln3_g  = (const float*)d_in[23];
    const float* ln3_b  = (const float*)d_in[24];
    const float* ff_w1  = (const float*)d_in[25];
    const float* ff_b1  = (const float*)d_in[26];
    const float* ff_w2  = (const float*)d_in[27];
    const float* ff_b2  = (const float*)d_in[28];
    float* out = (float*)d_out;

    float *xt, *xT, *pb1;
    __nv_bfloat16 *bbuf, *qkvh, *qh, *kvh2, *oh, *vfh, *ctxT;
    __nv_bfloat16 *wconv, *wqkv, *w1o, *w2q, *wkv2, *w2o, *wf1p, *wf2;
    cudaGetSymbolAddress((void**)&xt,   g_xt);
    cudaGetSymbolAddress((void**)&xT,   g_buf);
    cudaGetSymbolAddress((void**)&pb1,  g_pb1);
    cudaGetSymbolAddress((void**)&bbuf, g_bbuf);
    cudaGetSymbolAddress((void**)&qkvh, g_qkvh);
    cudaGetSymbolAddress((void**)&qh,   g_qh);
    cudaGetSymbolAddress((void**)&kvh2, g_kvh2);
    cudaGetSymbolAddress((void**)&oh,   g_oh);
    cudaGetSymbolAddress((void**)&vfh,  g_vfh);
    cudaGetSymbolAddress((void**)&ctxT, g_ctxT);
    cudaGetSymbolAddress((void**)&wconv, g_wconv);
    cudaGetSymbolAddress((void**)&wqkv, g_wqkv);
    cudaGetSymbolAddress((void**)&w1o,  g_w1o);
    cudaGetSymbolAddress((void**)&w2q,  g_w2q);
    cudaGetSymbolAddress((void**)&wkv2, g_wkv2);
    cudaGetSymbolAddress((void**)&w2o,  g_w2o);
    cudaGetSymbolAddress((void**)&wf1p, g_wf1p);
    cudaGetSymbolAddress((void**)&wf2,  g_wf2);

    const int MTOT = BSZ * NTOK;
    cudaStream_t s0 = 0;

    cudaStream_t s2;
    cudaStreamCreateWithFlags(&s2, cudaStreamNonBlocking);
    cudaEvent_t eFork, eConv, eKV;
    cudaEventCreateWithFlags(&eFork, cudaEventDisableTiming);
    cudaEventCreateWithFlags(&eConv, cudaEventDisableTiming);
    cudaEventCreateWithFlags(&eKV,   cudaEventDisableTiming);

    cudaEventRecord(eFork, s0);
    cudaStreamWaitEvent(s2, eFork, 0);

    // ---- side stream: weight conversion, ctx transpose, cross-KV projection ----
    {
        long tot4 = TOT_W / 4 + (2*DFF) / 4;
        int blocks = (int)((tot4 + 255) / 256);
        convert_all_kernel<<<blocks, 256, 0, s2>>>(conv_w, a1_wq, a1_wk, a1_wv, a1_wo,
                                                   a2_wq, a2_wk, a2_wv, a2_wo,
                                                   ff_w1, ff_w2, ff_b1);
    }
    cudaEventRecord(eConv, s2);
    ctx_transpose_kernel<<<dim3(MTOK/32, CDIM/32, BSZ), dim3(32, 8), 0, s2>>>(ctx, ctxT);
    launch_bb<1>(s2, ctxT, CDIM, wkv2, CDIM, kvh2, 2*INNER, nullptr, nullptr, 0,
                 BSZ*MTOK, 2*INNER, CDIM, 1.f);
    cudaEventRecord(eKV, s2);

    // ---- main stream: residual branch ----
    emb_kernel<<<BSZ * 16, 256, 0, s0>>>(emb, w_emb, b_emb);
    gn_stats_kernel<<<BSZ * GROUPS, 256, 0, s0>>>(x);
    gn_apply_t_kernel<<<dim3(NTOK/32, DIM/32, BSZ), dim3(32, 8), 0, s0>>>(x, gn_g, gn_b, bbuf, xT);
    cudaStreamWaitEvent(s0, eConv, 0);
    launch_bb<0>(s0, bbuf, DIM, wconv, DIM, xt, DIM, conv_b, xT, DIM,
                 MTOT, DIM, DIM, 1.f);

    // ---- self attention ----
    layernorm_kernel<<<MTOT, 256, 0, s0>>>(xt, bbuf, ln1_g, ln1_b);
    launch_bb<1>(s0, bbuf, DIM, wqkv, DIM, qkvh, 3*INNER, nullptr, nullptr, 0,
                 MTOT, 3*INNER, DIM, 1.f);
    flash_kernel<<<dim3(NTOK/64, BSZ*HEADS), 128, 0, s0>>>(
        qkvh, 3*INNER, qkvh + INNER, qkvh + 2*INNER, 3*INNER, oh,
        NTOK, (long)NTOK*3*INNER);
    launch_bb<0>(s0, oh, INNER, w1o, INNER, xt, DIM, a1_bo, xt, DIM, MTOT, DIM, INNER, 1.f);

    // ---- cross attention ----
    layernorm_kernel<<<MTOT, 256, 0, s0>>>(xt, bbuf, ln2_g, ln2_b);
    launch_bb<1>(s0, bbuf, DIM, w2q, DIM, qh, INNER, nullptr, nullptr, 0,
                 MTOT, INNER, DIM, 1.f);
    cudaStreamWaitEvent(s0, eKV, 0);
    flash_kernel<<<dim3(NTOK/64, BSZ*HEADS), 128, 0, s0>>>(
        qh, INNER, kvh2, kvh2 + INNER, 2*INNER, oh,
        MTOK, (long)MTOK*2*INNER);
    launch_bb<0>(s0, oh, INNER, w2o, INNER, xt, DIM, a2_bo, xt, DIM, MTOT, DIM, INNER, 1.f);

    // ---- GEGLU feed-forward ----
    layernorm_kernel<<<MTOT, 256, 0, s0>>>(xt, bbuf, ln3_g, ln3_b);
    launch_bb<2>(s0, bbuf, DIM, wf1p, DIM, vfh, DFF, pb1, nullptr, 0,
                 MTOT, 2*DFF, DIM, 1.f);
    launch_bb<3>(s0, vfh, DFF, wf2, DFF, out, 0, ff_b2, xt, DIM, MTOT, DIM, DFF, 1.f);
}

// round 15
// speedup vs baseline: 1.0039x; 1.0039x over previous
#include <cuda_runtime.h>
#include <cuda_bf16.h>
#include <math.h>
#include <stdint.h>

#define BSZ   8
#define DIM   512
#define NTOK  1024
#define EMBD  128
#define CDIM  512
#define MTOK  256
#define HEADS 8
#define DHEAD 64
#define INNER 512
#define DFF   2048
#define GROUPS 32

// ---------------- scratch (device globals; no allocations allowed) ----------
__device__ float g_xt [BSZ*NTOK*DIM];
__device__ float g_buf[BSZ*NTOK*DIM];
__device__ __nv_bfloat16 g_bbuf[BSZ*NTOK*DIM];
__device__ __nv_bfloat16 g_qkvh[BSZ*NTOK*3*INNER];
__device__ __nv_bfloat16 g_qh [BSZ*NTOK*INNER];
__device__ __nv_bfloat16 g_kvh2[BSZ*MTOK*2*INNER];
__device__ __nv_bfloat16 g_oh [BSZ*NTOK*INNER];
__device__ __nv_bfloat16 g_vfh[BSZ*NTOK*DFF];
__device__ __nv_bfloat16 g_ctxT[BSZ*MTOK*CDIM];
__device__ __nv_bfloat16 g_wconv[DIM*DIM];
__device__ __nv_bfloat16 g_wqkv[3*INNER*DIM];
__device__ __nv_bfloat16 g_w1o[DIM*INNER];
__device__ __nv_bfloat16 g_w2q[INNER*DIM];
__device__ __nv_bfloat16 g_wkv2[2*INNER*CDIM];
__device__ __nv_bfloat16 g_w2o[DIM*INNER];
__device__ __nv_bfloat16 g_wf1p[2*DFF*DIM];
__device__ __nv_bfloat16 g_wf2[DIM*DFF];
__device__ float g_pb1[2*DFF];
__device__ float g_scale[BSZ*DIM];
__device__ float g_shift[BSZ*DIM];
__device__ float g_gn_mu[BSZ*GROUPS];
__device__ float g_gn_rs[BSZ*GROUPS];

// ---------------- helpers ----------------------------------------------------
__device__ __forceinline__ float block_reduce_sum(float v, float* sh) {
    __syncthreads();
    #pragma unroll
    for (int o = 16; o > 0; o >>= 1) v += __shfl_xor_sync(0xffffffffu, v, o);
    int warp = threadIdx.x >> 5;
    if ((threadIdx.x & 31) == 0) sh[warp] = v;
    __syncthreads();
    int nw = blockDim.x >> 5;
    v = (threadIdx.x < nw) ? sh[threadIdx.x] : 0.f;
    if (threadIdx.x < 32) {
        #pragma unroll
        for (int o = 16; o > 0; o >>= 1) v += __shfl_xor_sync(0xffffffffu, v, o);
    }
    if (threadIdx.x == 0) sh[0] = v;
    __syncthreads();
    return sh[0];
}

__device__ __forceinline__ void mma16816(float* c, const uint32_t* a, const uint32_t* b) {
    asm volatile(
        "mma.sync.aligned.m16n8k16.row.col.f32.bf16.bf16.f32 "
        "{%0,%1,%2,%3}, {%4,%5,%6,%7}, {%8,%9}, {%0,%1,%2,%3};\n"
        : "+f"(c[0]), "+f"(c[1]), "+f"(c[2]), "+f"(c[3])
        : "r"(a[0]), "r"(a[1]), "r"(a[2]), "r"(a[3]), "r"(b[0]), "r"(b[1]));
}

__device__ __forceinline__ void ldsm4(uint32_t* r, uint32_t a) {
    asm volatile("ldmatrix.sync.aligned.m8n8.x4.shared.b16 {%0,%1,%2,%3}, [%4];\n"
        : "=r"(r[0]), "=r"(r[1]), "=r"(r[2]), "=r"(r[3]) : "r"(a));
}
__device__ __forceinline__ void ldsm4t(uint32_t* r, uint32_t a) {
    asm volatile("ldmatrix.sync.aligned.m8n8.x4.trans.shared.b16 {%0,%1,%2,%3}, [%4];\n"
        : "=r"(r[0]), "=r"(r[1]), "=r"(r[2]), "=r"(r[3]) : "r"(a));
}

__device__ __forceinline__ void cpa16(uint32_t s, const void* g) {
    asm volatile("cp.async.ca.shared.global [%0], [%1], 16;\n" :: "r"(s), "l"(g));
}
__device__ __forceinline__ void cpa_commit() { asm volatile("cp.async.commit_group;\n"); }
__device__ __forceinline__ void cpa_wait0()  { asm volatile("cp.async.wait_group 0;\n" ::: "memory"); }
__device__ __forceinline__ void cpa_wait1()  { asm volatile("cp.async.wait_group 1;\n" ::: "memory"); }

__device__ __forceinline__ float gelu_exact(float g) {
    return 0.5f * g * (1.f + erff(g * 0.70710678118654752f));
}

// ---------------- bf16 GEMM (OUT_MODE compile-time) ---------------------------
// OUT_MODE: 0 fp32 (+bias +Res), 1 bf16 (+bias), 2 geglu-bf16, 3 fp32-transposed
template<int BM, int BN, int WM, int WN, int OUT_MODE>
__global__ __launch_bounds__(256) void gemm_bb(
    const __nv_bfloat16* __restrict__ A, int lda,
    const __nv_bfloat16* __restrict__ Bm, int ldb,
    void* __restrict__ Cv, int ldc,
    const float* __restrict__ bias,
    const float* __restrict__ Res, int ldr,
    int K, float alpha)
{
    constexpr int BK = 32, AP = 40;
    constexpr int WARPS_N = BN / WN;
    constexpr int MT = WM / 16, NT = WN / 8;
    constexpr int ACH = BM * 4 / 256;
    constexpr int BCH = BN * 4 / 256;

    int i0 = blockIdx.y * BM, j0 = blockIdx.x * BN;
    __shared__ __align__(16) __nv_bfloat16 As[2][BM][AP];
    __shared__ __align__(16) __nv_bfloat16 Bs[2][BN][AP];
    uint32_t sA0 = (uint32_t)__cvta_generic_to_shared(&As[0][0][0]);
    uint32_t sB0 = (uint32_t)__cvta_generic_to_shared(&Bs[0][0][0]);

    int tid = threadIdx.x, warp = tid >> 5, lane = tid & 31;
    int g = lane >> 2, tg = lane & 3;
    int m_w = (warp / WARPS_N) * WM, n_w = (warp % WARPS_N) * WN;

    uint32_t aBase = sA0 + (uint32_t)(((m_w + (lane & 15)) * AP + ((lane >> 4) * 8)) * 2);
    uint32_t bBase = sB0 + (uint32_t)(((n_w + ((lane & 7) | ((lane & 16) >> 1))) * AP + (lane & 8)) * 2);

    float acc[MT][NT][4] = {};

    auto load_tiles = [&](int k0, int buf) {
        #pragma unroll
        for (int t = 0; t < ACH; t++) {
            int c = tid + t * 256;
            int row = c >> 2, off = (c & 3) * 8;
            cpa16(sA0 + buf * (BM * AP * 2) + (row * AP + off) * 2,
                  A + (long)(i0 + row) * lda + k0 + off);
        }
        #pragma unroll
        for (int t = 0; t < BCH; t++) {
            int c = tid + t * 256;
            int row = c >> 2, off = (c & 3) * 8;
            cpa16(sB0 + buf * (BN * AP * 2) + (row * AP + off) * 2,
                  Bm + (long)(j0 + row) * ldb + k0 + off);
        }
        cpa_commit();
    };

    load_tiles(0, 0);
    cpa_wait0();
    __syncthreads();

    int KB = K / BK;
    for (int kb = 0; kb < KB; kb++) {
        int cur = kb & 1;
        if (kb + 1 < KB) load_tiles((kb + 1) * BK, cur ^ 1);
        uint32_t aB = aBase + cur * (BM * AP * 2);
        uint32_t bB = bBase + cur * (BN * AP * 2);
        uint32_t af[2][MT][4];
        uint32_t bf[2][NT][2];
        #pragma unroll
        for (int ks2 = 0; ks2 < 2; ks2++) {
            #pragma unroll
            for (int mt = 0; mt < MT; mt++)
                ldsm4(af[ks2][mt], aB + (mt * 16 * AP + ks2 * 16) * 2);
            #pragma unroll
            for (int p = 0; p < NT / 2; p++) {
                uint32_t r[4];
                ldsm4(r, bB + (p * 16 * AP + ks2 * 16) * 2);
                bf[ks2][2*p][0] = r[0]; bf[ks2][2*p][1] = r[1];
                bf[ks2][2*p+1][0] = r[2]; bf[ks2][2*p+1][1] = r[3];
            }
        }
        #pragma unroll
        for (int ks2 = 0; ks2 < 2; ks2++)
            #pragma unroll
            for (int mt = 0; mt < MT; mt++)
                #pragma unroll
                for (int nt = 0; nt < NT; nt++)
                    mma16816(acc[mt][nt], af[ks2][mt], bf[ks2][nt]);
        if (kb + 1 < KB) cpa_wait0();
        __syncthreads();
    }

    float* Cf = reinterpret_cast<float*>(Cv);
    __nv_bfloat16* Ch = reinterpret_cast<__nv_bfloat16*>(Cv);

    if (OUT_MODE == 3) {
        constexpr int SP = 33;
        float* stage = reinterpret_cast<float*>(&As[0][0][0]);
        int bb = i0 >> 10;
        int nbase = i0 & (NTOK - 1);
        #pragma unroll
        for (int pass = 0; pass < 4; pass++) {
            __syncthreads();
            int rlo = pass * 32;
            #pragma unroll
            for (int mt = 0; mt < MT; mt++) {
                #pragma unroll
                for (int h = 0; h < 2; h++) {
                    int il = m_w + mt*16 + g + 8*h;
                    if (il >= rlo && il < rlo + 32) {
                        #pragma unroll
                        for (int nt = 0; nt < NT; nt++) {
                            int j = n_w + nt*8 + tg*2;
                            float v0 = alpha * acc[mt][nt][2*h]   + bias[j0 + j];
                            float v1 = alpha * acc[mt][nt][2*h+1] + bias[j0 + j + 1];
                            const float* rp = &Res[(long)(i0 + il) * ldr + j0 + j];
                            v0 += rp[0]; v1 += rp[1];
                            stage[j * SP + (il & 31)]       = v0;
                            stage[(j + 1) * SP + (il & 31)] = v1;
                        }
                    }
                }
            }
            __syncthreads();
            for (int q = tid; q < BN * 2; q += 256) {
                int c = q >> 1, half = q & 1;
                float* op = &Cf[((long)bb * DIM + j0 + c) * NTOK + nbase + rlo + half*16];
                float* sp = &stage[c * SP + half * 16];
                #pragma unroll
                for (int s = 0; s < 4; s++) {
                    ((float4*)op)[s] = make_float4(sp[s*4], sp[s*4+1], sp[s*4+2], sp[s*4+3]);
                }
            }
        }
        return;
    }

    #pragma unroll
    for (int mt = 0; mt < MT; mt++) {
        #pragma unroll
        for (int h = 0; h < 2; h++) {
            int i = i0 + m_w + mt*16 + g + 8*h;
            #pragma unroll
            for (int nt = 0; nt < NT; nt++) {
                int j = j0 + n_w + nt*8 + tg*2;
                float v0 = alpha * acc[mt][nt][2*h+0];
                float v1 = alpha * acc[mt][nt][2*h+1];
                if (bias) { v0 += bias[j]; v1 += bias[j+1]; }
                if (OUT_MODE == 2) {
                    Ch[(long)i * ldc + (j >> 1)] = __float2bfloat16_rn(v0 * gelu_exact(v1));
                } else if (OUT_MODE == 1) {
                    *reinterpret_cast<__nv_bfloat162*>(&Ch[(long)i * ldc + j]) =
                        __floats2bfloat162_rn(v0, v1);
                } else {
                    if (Res) {
                        const float* rp = &Res[(long)i * ldr + j];
                        v0 += rp[0]; v1 += rp[1];
                    }
                    *reinterpret_cast<float2*>(&Cf[(long)i * ldc + j]) = make_float2(v0, v1);
                }
            }
        }
    }
}

// ---------------- fused flash attention (cp.async K/V pipeline) ---------------
#define FPITCH 72
#define FTILEB (64 * FPITCH * 2)
__global__ __launch_bounds__(128) void flash_kernel(
    const __nv_bfloat16* __restrict__ Q, int q_ld,
    const __nv_bfloat16* __restrict__ K,
    const __nv_bfloat16* __restrict__ V, int kv_ld,
    __nv_bfloat16* __restrict__ O,
    int nk, long kv_bstride)
{
    __shared__ __align__(16) __nv_bfloat16 Qs[64][FPITCH];
    __shared__ __align__(16) __nv_bfloat16 Ks[2][64][FPITCH];
    __shared__ __align__(16) __nv_bfloat16 Vs[2][64][FPITCH];
    uint32_t sQ = (uint32_t)__cvta_generic_to_shared(&Qs[0][0]);
    uint32_t sK = (uint32_t)__cvta_generic_to_shared(&Ks[0][0][0]);
    uint32_t sV = (uint32_t)__cvta_generic_to_shared(&Vs[0][0][0]);

    int tid = threadIdx.x, warp = tid >> 5, lane = tid & 31;
    int g = lane >> 2, tg = lane & 3;
    int b = blockIdx.y / HEADS, h = blockIdx.y % HEADS;
    const __nv_bfloat16* qb = Q + ((long)b*NTOK + blockIdx.x*64)*q_ld + h*DHEAD;
    const __nv_bfloat16* kb = K + (long)b*kv_bstride + h*DHEAD;
    const __nv_bfloat16* vb = V + (long)b*kv_bstride + h*DHEAD;
    __nv_bfloat16* ob = O + ((long)b*NTOK + blockIdx.x*64)*INNER + h*DHEAD;

    int mrow = warp * 16;
    uint32_t qBase = sQ + (uint32_t)(((mrow + (lane & 15)) * FPITCH + (lane >> 4) * 8) * 2);
    uint32_t kBase = sK + (uint32_t)((((lane & 7) | ((lane & 16) >> 1)) * FPITCH + (lane & 8)) * 2);
    uint32_t vBase = sV + (uint32_t)(((((lane >> 3) & 1) * 8 + (lane & 7)) * FPITCH + (lane >> 4) * 8) * 2);

    auto pf = [&](int kt, int buf) {
        #pragma unroll
        for (int t = 0; t < 4; t++) {
            int c = tid + t*128;
            int r = c >> 3, c8 = (c & 7) * 8;
            cpa16(sK + buf*FTILEB + (r*FPITCH + c8)*2, kb + (long)(kt + r)*kv_ld + c8);
            cpa16(sV + buf*FTILEB + (r*FPITCH + c8)*2, vb + (long)(kt + r)*kv_ld + c8);
        }
        cpa_commit();
    };

    #pragma unroll
    for (int t = 0; t < 4; t++) {
        int c = tid + t*128;
        int r = c >> 3, c8 = (c & 7) * 8;
        *reinterpret_cast<uint4*>(&Qs[r][c8]) =
            *reinterpret_cast<const uint4*>(&qb[(long)r*q_ld + c8]);
    }
    pf(0, 0);
    if (nk > 64) pf(64, 1);

    float m_i[2] = {-1e30f, -1e30f}, l_i[2] = {0.f, 0.f};
    float oa[8][4];
    #pragma unroll
    for (int nt = 0; nt < 8; nt++) { oa[nt][0]=0.f; oa[nt][1]=0.f; oa[nt][2]=0.f; oa[nt][3]=0.f; }

    __syncthreads();

    uint32_t qf[4][4];
    #pragma unroll
    for (int kc = 0; kc < 4; kc++)
        ldsm4(qf[kc], qBase + kc * 16 * 2);

    int T = nk >> 6;
    for (int t = 0; t < T; t++) {
        int buf = t & 1;
        if (t + 1 < T) cpa_wait1(); else cpa_wait0();
        __syncthreads();
        uint32_t kB = kBase + buf*FTILEB;
        uint32_t vB = vBase + buf*FTILEB;

        float s[8][4] = {};
        #pragma unroll
        for (int kc = 0; kc < 4; kc++) {
            uint32_t bk[8][2];
            #pragma unroll
            for (int p = 0; p < 4; p++) {
                uint32_t r[4];
                ldsm4(r, kB + (p * 16 * FPITCH + kc * 16) * 2);
                bk[2*p][0] = r[0]; bk[2*p][1] = r[1];
                bk[2*p+1][0] = r[2]; bk[2*p+1][1] = r[3];
            }
            #pragma unroll
            for (int nt = 0; nt < 8; nt++)
                mma16816(s[nt], qf[kc], bk[nt]);
        }

        #pragma unroll
        for (int h2 = 0; h2 < 2; h2++) {
            float mt = -1e30f;
            #pragma unroll
            for (int nt = 0; nt < 8; nt++)
                mt = fmaxf(mt, fmaxf(s[nt][2*h2], s[nt][2*h2+1]));
            mt = fmaxf(mt, __shfl_xor_sync(0xffffffffu, mt, 1));
            mt = fmaxf(mt, __shfl_xor_sync(0xffffffffu, mt, 2));
            float mnew = fmaxf(m_i[h2], mt);
            float corr = __expf(m_i[h2] - mnew);
            m_i[h2] = mnew;
            float lsum = 0.f;
            #pragma unroll
            for (int nt = 0; nt < 8; nt++) {
                float e0 = __expf(s[nt][2*h2]   - mnew);
                float e1 = __expf(s[nt][2*h2+1] - mnew);
                s[nt][2*h2] = e0; s[nt][2*h2+1] = e1;
                lsum += e0 + e1;
            }
            lsum += __shfl_xor_sync(0xffffffffu, lsum, 1);
            lsum += __shfl_xor_sync(0xffffffffu, lsum, 2);
            l_i[h2] = l_i[h2] * corr + lsum;
            #pragma unroll
            for (int nt = 0; nt < 8; nt++) { oa[nt][2*h2] *= corr; oa[nt][2*h2+1] *= corr; }
        }

        #pragma unroll
        for (int kc = 0; kc < 4; kc++) {
            uint32_t ap[4];
            __nv_bfloat162 t0 = __floats2bfloat162_rn(s[2*kc][0],   s[2*kc][1]);
            __nv_bfloat162 t1 = __floats2bfloat162_rn(s[2*kc][2],   s[2*kc][3]);
            __nv_bfloat162 t2 = __floats2bfloat162_rn(s[2*kc+1][0], s[2*kc+1][1]);
            __nv_bfloat162 t3 = __floats2bfloat162_rn(s[2*kc+1][2], s[2*kc+1][3]);
            ap[0] = *reinterpret_cast<uint32_t*>(&t0);
            ap[1] = *reinterpret_cast<uint32_t*>(&t1);
            ap[2] = *reinterpret_cast<uint32_t*>(&t2);
            ap[3] = *reinterpret_cast<uint32_t*>(&t3);
            uint32_t bv[8][2];
            #pragma unroll
            for (int p = 0; p < 4; p++) {
                uint32_t r[4];
                ldsm4t(r, vB + (kc * 16 * FPITCH + p * 16) * 2);
                bv[2*p][0] = r[0]; bv[2*p][1] = r[1];
                bv[2*p+1][0] = r[2]; bv[2*p+1][1] = r[3];
            }
            #pragma unroll
            for (int nt = 0; nt < 8; nt++)
                mma16816(oa[nt], ap, bv[nt]);
        }
        __syncthreads();
        if (t + 2 < T) pf((t + 2) * 64, buf);
    }

    #pragma unroll
    for (int h2 = 0; h2 < 2; h2++) {
        float inv = 1.f / l_i[h2];
        int r = mrow + g + 8*h2;
        #pragma unroll
        for (int nt = 0; nt < 8; nt++) {
            *reinterpret_cast<__nv_bfloat162*>(&ob[(long)r*INNER + nt*8 + tg*2]) =
                __floats2bfloat162_rn(oa[nt][2*h2] * inv, oa[nt][2*h2+1] * inv);
        }
    }
}

// ---------------- fused weight conversion -------------------------------------
#define SQW (INNER*DIM)
#define N_CONV  (DIM*DIM)
#define N_WF1   (2*DFF*DIM)
#define N_WF2   (DIM*DFF)
#define TOT_W   (N_CONV + 3*SQW + SQW + SQW + 2*SQW + SQW + N_WF1 + N_WF2)
__global__ void convert_all_kernel(
    const float* __restrict__ conv_w,
    const float* __restrict__ a1q, const float* __restrict__ a1k,
    const float* __restrict__ a1v, const float* __restrict__ a1o,
    const float* __restrict__ a2q, const float* __restrict__ a2k,
    const float* __restrict__ a2v, const float* __restrict__ a2o,
    const float* __restrict__ f1,  const float* __restrict__ f2,
    const float* __restrict__ b1)
{
    long i = (long)(blockIdx.x * 256 + threadIdx.x) * 4;
    auto cvt = [](const float* s, __nv_bfloat16* d, long si, long di, float sc) {
        float4 v = *reinterpret_cast<const float4*>(s + si);
        *reinterpret_cast<__nv_bfloat162*>(d + di)     = __floats2bfloat162_rn(v.x*sc, v.y*sc);
        *reinterpret_cast<__nv_bfloat162*>(d + di + 2) = __floats2bfloat162_rn(v.z*sc, v.w*sc);
    };
    if (i < N_CONV) { cvt(conv_w, g_wconv, i, i, 1.f); return; }
    i -= N_CONV;
    if (i < SQW)    { cvt(a1q, g_wqkv, i, i, 0.125f); return; }
    i -= SQW;
    if (i < SQW)    { cvt(a1k, g_wqkv, i, i + SQW, 1.f); return; }
    i -= SQW;
    if (i < SQW)    { cvt(a1v, g_wqkv, i, i + 2*SQW, 1.f); return; }
    i -= SQW;
    if (i < SQW)    { cvt(a1o, g_w1o, i, i, 1.f); return; }
    i -= SQW;
    if (i < SQW)    { cvt(a2q, g_w2q, i, i, 0.125f); return; }
    i -= SQW;
    if (i < SQW)    { cvt(a2k, g_wkv2, i, i, 1.f); return; }
    i -= SQW;
    if (i < SQW)    { cvt(a2v, g_wkv2, i, i + SQW, 1.f); return; }
    i -= SQW;
    if (i < SQW)    { cvt(a2o, g_w2o, i, i, 1.f); return; }
    i -= SQW;
    if (i < N_WF1) {
        int row = (int)(i / DIM), col = (int)(i % DIM);
        int srow = (row >> 1) + (row & 1) * DFF;
        cvt(f1, g_wf1p, (long)srow * DIM + col, i, 1.f);
        return;
    }
    i -= N_WF1;
    if (i < N_WF2)  { cvt(f2, g_wf2, i, i, 1.f); return; }
    i -= N_WF2;
    if (i < 2*DFF) {
        #pragma unroll
        for (int s = 0; s < 4; s++) {
            long o = i + s;
            g_pb1[o] = b1[(o >> 1) + (o & 1) * DFF];
        }
    }
}

// ---------------- small kernels ----------------------------------------------
__global__ __launch_bounds__(256) void emb_kernel(
    const float* __restrict__ emb,
    const float* __restrict__ w,
    const float* __restrict__ bias)
{
    int b = blockIdx.x >> 4, chunk = blockIdx.x & 15;
    __shared__ float e[EMBD];
    int tid = threadIdx.x, warp = tid >> 5, lane = tid & 31;
    if (tid < EMBD) {
        float v = emb[b * EMBD + tid];
        e[tid] = v / (1.f + __expf(-v));
    }
    __syncthreads();
    float4 ev = reinterpret_cast<const float4*>(e)[lane];
    #pragma unroll
    for (int q = 0; q < 8; q++) {
        int o = chunk * 64 + warp * 8 + q;     // 0..1023
        float4 wv = reinterpret_cast<const float4*>(w + (long)o * EMBD)[lane];
        float p = wv.x*ev.x + wv.y*ev.y + wv.z*ev.z + wv.w*ev.w;
        #pragma unroll
        for (int s = 16; s > 0; s >>= 1) p += __shfl_xor_sync(0xffffffffu, p, s);
        if (lane == 0) {
            float acc = p + bias[o];
            if (o < DIM) g_scale[b * DIM + o] = 1.f + acc;
            else         g_shift[b * DIM + (o - DIM)] = acc;
        }
    }
}

__global__ void gn_stats_kernel(const float* __restrict__ X)
{
    __shared__ float sh[32];
    int b = blockIdx.x / GROUPS, g = blockIdx.x % GROUPS;
    const int CH = DIM / GROUPS;
    const float* p = X + ((long)b * DIM + (long)g * CH) * NTOK;
    float s = 0.f, ss = 0.f;
    for (int i = threadIdx.x; i < CH * NTOK / 4; i += blockDim.x) {
        float4 v = reinterpret_cast<const float4*>(p)[i];
        s  += v.x + v.y + v.z + v.w;
        ss += v.x*v.x + v.y*v.y + v.z*v.z + v.w*v.w;
    }
    s  = block_reduce_sum(s, sh);
    ss = block_reduce_sum(ss, sh);
    if (threadIdx.x == 0) {
        float inv = 1.f / (CH * NTOK);
        float mu = s * inv;
        float var = ss * inv - mu * mu;
        g_gn_mu[blockIdx.x] = mu;
        g_gn_rs[blockIdx.x] = rsqrtf(var + 1e-6f);
    }
}

__global__ void gn_apply_t_kernel(const float* __restrict__ X,
                                  const float* __restrict__ gn_g,
                                  const float* __restrict__ gn_b,
                                  __nv_bfloat16* __restrict__ HT,
                                  float* __restrict__ XT)
{
    __shared__ float tile[32][33];
    int b = blockIdx.z;
    int n0 = blockIdx.x * 32, c0 = blockIdx.y * 32;
    for (int r = threadIdx.y; r < 32; r += 8)
        tile[r][threadIdx.x] = X[((long)b * DIM + c0 + r) * NTOK + n0 + threadIdx.x];
    __syncthreads();
    int c = c0 + threadIdx.x;
    int grp = b * GROUPS + (c >> 4);
    float mu = g_gn_mu[grp], rs = g_gn_rs[grp];
    float gg = gn_g[c], bb = gn_b[c];
    float sc = g_scale[b * DIM + c], sf = g_shift[b * DIM + c];
    for (int r = threadIdx.y; r < 32; r += 8) {
        int n = n0 + r;
        float raw = tile[threadIdx.x][r];
        float v = (raw - mu) * rs * gg + bb;
        v = v * sc + sf;
        float s = v / (1.f + __expf(-v));
        HT[((long)b * NTOK + n) * DIM + c] = __float2bfloat16_rn(s);
        XT[((long)b * NTOK + n) * DIM + c] = raw;
    }
}

__global__ void ctx_transpose_kernel(const float* __restrict__ CTX,
                                     __nv_bfloat16* __restrict__ CT)
{
    __shared__ float tile[32][33];
    int b = blockIdx.z;
    int m0 = blockIdx.x * 32, c0 = blockIdx.y * 32;
    for (int r = threadIdx.y; r < 32; r += 8)
        tile[r][threadIdx.x] = CTX[((long)b * CDIM + c0 + r) * MTOK + m0 + threadIdx.x];
    __syncthreads();
    for (int r = threadIdx.y; r < 32; r += 8)
        CT[((long)b * MTOK + m0 + r) * CDIM + c0 + threadIdx.x] =
            __float2bfloat16_rn(tile[threadIdx.x][r]);
}

__global__ void layernorm_kernel(const float* __restrict__ X, __nv_bfloat16* __restrict__ Y,
                                 const float* __restrict__ g, const float* __restrict__ b)
{
    __shared__ float sh[32];
    long t = blockIdx.x;
    const float* x = X + t * DIM;
    __nv_bfloat16* y = Y + t * DIM;
    float s = 0.f, ss = 0.f;
    for (int i = threadIdx.x; i < DIM; i += blockDim.x) {
        float v = x[i]; s += v; ss += v * v;
    }
    s  = block_reduce_sum(s, sh);
    ss = block_reduce_sum(ss, sh);
    float mu = s * (1.f / DIM);
    float var = ss * (1.f / DIM) - mu * mu;
    float rs = rsqrtf(var + 1e-5f);
    for (int i = threadIdx.x; i < DIM; i += blockDim.x)
        y[i] = __float2bfloat16_rn((x[i] - mu) * rs * g[i] + b[i]);
}

// ---------------- host orchestration ----------------------------------------
template<int OUT_MODE>
static void launch_bb(cudaStream_t st,
                      const __nv_bfloat16* A, int lda, const __nv_bfloat16* B, int ldb,
                      void* C, int ldc, const float* bias, const float* R, int ldr,
                      int M, int N, int K, float alpha)
{
    dim3 grid(N / 128, M / 128);
    gemm_bb<128,128,64,32,OUT_MODE><<<grid, 256, 0, st>>>(A, lda, B, ldb, C, ldc,
                                                          bias, R, ldr, K, alpha);
}

extern "C" void kernel_launch(void* const* d_in, const int* in_sizes, int n_in,
                              void* d_out, int out_size)
{
    const float* x      = (const float*)d_in[0];
    const float* emb    = (const float*)d_in[1];
    const float* ctx    = (const float*)d_in[2];
    const float* w_emb  = (const float*)d_in[3];
    const float* b_emb  = (const float*)d_in[4];
    const float* gn_g   = (const float*)d_in[5];
    const float* gn_b   = (const float*)d_in[6];
    const float* conv_w = (const float*)d_in[7];
    const float* conv_b = (const float*)d_in[8];
    const float* a1_wq  = (const float*)d_in[9];
    const float* a1_wk  = (const float*)d_in[10];
    const float* a1_wv  = (const float*)d_in[11];
    const float* a1_wo  = (const float*)d_in[12];
    const float* a1_bo  = (const float*)d_in[13];
    const float* a2_wq  = (const float*)d_in[14];
    const float* a2_wk  = (const float*)d_in[15];
    const float* a2_wv  = (const float*)d_in[16];
    const float* a2_wo  = (const float*)d_in[17];
    const float* a2_bo  = (const float*)d_in[18];
    const float* ln1_g  = (const float*)d_in[19];
    const float* ln1_b  = (const float*)d_in[20];
    const float* ln2_g  = (const float*)d_in[21];
    const float* ln2_b  = (const float*)d_in[22];
    const float* ln3_g  = (const float*)d_in[23];
    const float* ln3_b  = (const float*)d_in[24];
    const float* ff_w1  = (const float*)d_in[25];
    const float* ff_b1  = (const float*)d_in[26];
    const float* ff_w2  = (const float*)d_in[27];
    const float* ff_b2  = (const float*)d_in[28];
    float* out = (float*)d_out;

    float *xt, *xT, *pb1;
    __nv_bfloat16 *bbuf, *qkvh, *qh, *kvh2, *oh, *vfh, *ctxT;
    __nv_bfloat16 *wconv, *wqkv, *w1o, *w2q, *wkv2, *w2o, *wf1p, *wf2;
    cudaGetSymbolAddress((void**)&xt,   g_xt);
    cudaGetSymbolAddress((void**)&xT,   g_buf);
    cudaGetSymbolAddress((void**)&pb1,  g_pb1);
    cudaGetSymbolAddress((void**)&bbuf, g_bbuf);
    cudaGetSymbolAddress((void**)&qkvh, g_qkvh);
    cudaGetSymbolAddress((void**)&qh,   g_qh);
    cudaGetSymbolAddress((void**)&kvh2, g_kvh2);
    cudaGetSymbolAddress((void**)&oh,   g_oh);
    cudaGetSymbolAddress((void**)&vfh,  g_vfh);
    cudaGetSymbolAddress((void**)&ctxT, g_ctxT);
    cudaGetSymbolAddress((void**)&wconv, g_wconv);
    cudaGetSymbolAddress((void**)&wqkv, g_wqkv);
    cudaGetSymbolAddress((void**)&w1o,  g_w1o);
    cudaGetSymbolAddress((void**)&w2q,  g_w2q);
    cudaGetSymbolAddress((void**)&wkv2, g_wkv2);
    cudaGetSymbolAddress((void**)&w2o,  g_w2o);
    cudaGetSymbolAddress((void**)&wf1p, g_wf1p);
    cudaGetSymbolAddress((void**)&wf2,  g_wf2);

    const int MTOT = BSZ * NTOK;
    cudaStream_t s0 = 0;

    cudaStream_t s2;
    cudaStreamCreateWithFlags(&s2, cudaStreamNonBlocking);
    cudaEvent_t eFork, eConv, eKV;
    cudaEventCreateWithFlags(&eFork, cudaEventDisableTiming);
    cudaEventCreateWithFlags(&eConv, cudaEventDisableTiming);
    cudaEventCreateWithFlags(&eKV,   cudaEventDisableTiming);

    cudaEventRecord(eFork, s0);
    cudaStreamWaitEvent(s2, eFork, 0);

    // ---- side stream: weight conversion, ctx transpose, cross-KV projection ----
    {
        long tot4 = TOT_W / 4 + (2*DFF) / 4;
        int blocks = (int)((tot4 + 255) / 256);
        convert_all_kernel<<<blocks, 256, 0, s2>>>(conv_w, a1_wq, a1_wk, a1_wv, a1_wo,
                                                   a2_wq, a2_wk, a2_wv, a2_wo,
                                                   ff_w1, ff_w2, ff_b1);
    }
    cudaEventRecord(eConv, s2);
    ctx_transpose_kernel<<<dim3(MTOK/32, CDIM/32, BSZ), dim3(32, 8), 0, s2>>>(ctx, ctxT);
    launch_bb<1>(s2, ctxT, CDIM, wkv2, CDIM, kvh2, 2*INNER, nullptr, nullptr, 0,
                 BSZ*MTOK, 2*INNER, CDIM, 1.f);
    cudaEventRecord(eKV, s2);

    // ---- main stream: residual branch ----
    emb_kernel<<<BSZ * 16, 256, 0, s0>>>(emb, w_emb, b_emb);
    gn_stats_kernel<<<BSZ * GROUPS, 256, 0, s0>>>(x);
    gn_apply_t_kernel<<<dim3(NTOK/32, DIM/32, BSZ), dim3(32, 8), 0, s0>>>(x, gn_g, gn_b, bbuf, xT);
    cudaStreamWaitEvent(s0, eConv, 0);
    launch_bb<0>(s0, bbuf, DIM, wconv, DIM, xt, DIM, conv_b, xT, DIM,
                 MTOT, DIM, DIM, 1.f);

    // ---- self attention ----
    layernorm_kernel<<<MTOT, 256, 0, s0>>>(xt, bbuf, ln1_g, ln1_b);
    launch_bb<1>(s0, bbuf, DIM, wqkv, DIM, qkvh, 3*INNER, nullptr, nullptr, 0,
                 MTOT, 3*INNER, DIM, 1.f);
    flash_kernel<<<dim3(NTOK/64, BSZ*HEADS), 128, 0, s0>>>(
        qkvh, 3*INNER, qkvh + INNER, qkvh + 2*INNER, 3*INNER, oh,
        NTOK, (long)NTOK*3*INNER);
    launch_bb<0>(s0, oh, INNER, w1o, INNER, xt, DIM, a1_bo, xt, DIM, MTOT, DIM, INNER, 1.f);

    // ---- cross attention ----
    layernorm_kernel<<<MTOT, 256, 0, s0>>>(xt, bbuf, ln2_g, ln2_b);
    launch_bb<1>(s0, bbuf, DIM, w2q, DIM, qh, INNER, nullptr, nullptr, 0,
                 MTOT, INNER, DIM, 1.f);
    cudaStreamWaitEvent(s0, eKV, 0);
    flash_kernel<<<dim3(NTOK/64, BSZ*HEADS), 128, 0, s0>>>(
        qh, INNER, kvh2, kvh2 + INNER, 2*INNER, oh,
        MTOK, (long)MTOK*2*INNER);
    launch_bb<0>(s0, oh, INNER, w2o, INNER, xt, DIM, a2_bo, xt, DIM, MTOT, DIM, INNER, 1.f);

    // ---- GEGLU feed-forward ----
    layernorm_kernel<<<MTOT, 256, 0, s0>>>(xt, bbuf, ln3_g, ln3_b);
    launch_bb<2>(s0, bbuf, DIM, wf1p, DIM, vfh, DFF, pb1, nullptr, 0,
                 MTOT, 2*DFF, DIM, 1.f);
    launch_bb<3>(s0, vfh, DFF, wf2, DFF, out, 0, ff_b2, xt, DIM, MTOT, DIM, DFF, 1.f);
}

// round 16
// speedup vs baseline: 1.5211x; 1.5153x over previous
#include <cuda_runtime.h>
#include <cuda_bf16.h>
#include <math.h>
#include <stdint.h>

#define BSZ   8
#define DIM   512
#define NTOK  1024
#define EMBD  128
#define CDIM  512
#define MTOK  256
#define HEADS 8
#define DHEAD 64
#define INNER 512
#define DFF   2048
#define GROUPS 32

// ---------------- scratch (device globals; no allocations allowed) ----------
__device__ float g_xt [BSZ*NTOK*DIM];
__device__ float g_buf[BSZ*NTOK*DIM];
__device__ __nv_bfloat16 g_bbuf[BSZ*NTOK*DIM];
__device__ __nv_bfloat16 g_qkvh[BSZ*NTOK*3*INNER];
__device__ __nv_bfloat16 g_qh [BSZ*NTOK*INNER];
__device__ __nv_bfloat16 g_kvh2[BSZ*MTOK*2*INNER];
__device__ __nv_bfloat16 g_oh [BSZ*NTOK*INNER];
__device__ __nv_bfloat16 g_vfh[BSZ*NTOK*DFF];
__device__ __nv_bfloat16 g_ctxT[BSZ*MTOK*CDIM];
__device__ __nv_bfloat16 g_wconv[DIM*DIM];
__device__ __nv_bfloat16 g_wqkv[3*INNER*DIM];
__device__ __nv_bfloat16 g_w1o[DIM*INNER];
__device__ __nv_bfloat16 g_w2q[INNER*DIM];
__device__ __nv_bfloat16 g_wkv2[2*INNER*CDIM];
__device__ __nv_bfloat16 g_w2o[DIM*INNER];
__device__ __nv_bfloat16 g_wf1p[2*DFF*DIM];
__device__ __nv_bfloat16 g_wf2[DIM*DFF];
__device__ float g_pb1[2*DFF];
__device__ float g_scale[BSZ*DIM];
__device__ float g_shift[BSZ*DIM];
__device__ float g_gn_mu[BSZ*GROUPS];
__device__ float g_gn_rs[BSZ*GROUPS];

// ---------------- helpers ----------------------------------------------------
__device__ __forceinline__ float block_reduce_sum(float v, float* sh) {
    __syncthreads();
    #pragma unroll
    for (int o = 16; o > 0; o >>= 1) v += __shfl_xor_sync(0xffffffffu, v, o);
    int warp = threadIdx.x >> 5;
    if ((threadIdx.x & 31) == 0) sh[warp] = v;
    __syncthreads();
    int nw = blockDim.x >> 5;
    v = (threadIdx.x < nw) ? sh[threadIdx.x] : 0.f;
    if (threadIdx.x < 32) {
        #pragma unroll
        for (int o = 16; o > 0; o >>= 1) v += __shfl_xor_sync(0xffffffffu, v, o);
    }
    if (threadIdx.x == 0) sh[0] = v;
    __syncthreads();
    return sh[0];
}

__device__ __forceinline__ void mma16816(float* c, const uint32_t* a, const uint32_t* b) {
    asm volatile(
        "mma.sync.aligned.m16n8k16.row.col.f32.bf16.bf16.f32 "
        "{%0,%1,%2,%3}, {%4,%5,%6,%7}, {%8,%9}, {%0,%1,%2,%3};\n"
        : "+f"(c[0]), "+f"(c[1]), "+f"(c[2]), "+f"(c[3])
        : "r"(a[0]), "r"(a[1]), "r"(a[2]), "r"(a[3]), "r"(b[0]), "r"(b[1]));
}

__device__ __forceinline__ void ldsm4(uint32_t* r, uint32_t a) {
    asm volatile("ldmatrix.sync.aligned.m8n8.x4.shared.b16 {%0,%1,%2,%3}, [%4];\n"
        : "=r"(r[0]), "=r"(r[1]), "=r"(r[2]), "=r"(r[3]) : "r"(a));
}
__device__ __forceinline__ void ldsm4t(uint32_t* r, uint32_t a) {
    asm volatile("ldmatrix.sync.aligned.m8n8.x4.trans.shared.b16 {%0,%1,%2,%3}, [%4];\n"
        : "=r"(r[0]), "=r"(r[1]), "=r"(r[2]), "=r"(r[3]) : "r"(a));
}

__device__ __forceinline__ void cpa16(uint32_t s, const void* g) {
    asm volatile("cp.async.ca.shared.global [%0], [%1], 16;\n" :: "r"(s), "l"(g));
}
__device__ __forceinline__ void cpa_commit() { asm volatile("cp.async.commit_group;\n"); }
__device__ __forceinline__ void cpa_wait0()  { asm volatile("cp.async.wait_group 0;\n" ::: "memory"); }
__device__ __forceinline__ void cpa_wait1()  { asm volatile("cp.async.wait_group 1;\n" ::: "memory"); }

__device__ __forceinline__ float gelu_exact(float g) {
    return 0.5f * g * (1.f + erff(g * 0.70710678118654752f));
}

// ---------------- bf16 GEMM (OUT_MODE compile-time) ---------------------------
// OUT_MODE: 0 fp32 (+bias +Res), 1 bf16 (+bias), 2 geglu-bf16, 3 fp32-transposed
template<int BM, int BN, int WM, int WN, int OUT_MODE>
__global__ __launch_bounds__(256) void gemm_bb(
    const __nv_bfloat16* __restrict__ A, int lda,
    const __nv_bfloat16* __restrict__ Bm, int ldb,
    void* __restrict__ Cv, int ldc,
    const float* __restrict__ bias,
    const float* __restrict__ Res, int ldr,
    int K, float alpha)
{
    constexpr int BK = 32, AP = 40;
    constexpr int WARPS_N = BN / WN;
    constexpr int MT = WM / 16, NT = WN / 8;
    constexpr int ACH = BM * 4 / 256;
    constexpr int BCH = BN * 4 / 256;

    int i0 = blockIdx.y * BM, j0 = blockIdx.x * BN;
    __shared__ __align__(16) __nv_bfloat16 As[2][BM][AP];
    __shared__ __align__(16) __nv_bfloat16 Bs[2][BN][AP];
    uint32_t sA0 = (uint32_t)__cvta_generic_to_shared(&As[0][0][0]);
    uint32_t sB0 = (uint32_t)__cvta_generic_to_shared(&Bs[0][0][0]);

    int tid = threadIdx.x, warp = tid >> 5, lane = tid & 31;
    int g = lane >> 2, tg = lane & 3;
    int m_w = (warp / WARPS_N) * WM, n_w = (warp % WARPS_N) * WN;

    uint32_t aBase = sA0 + (uint32_t)(((m_w + (lane & 15)) * AP + ((lane >> 4) * 8)) * 2);
    uint32_t bBase = sB0 + (uint32_t)(((n_w + ((lane & 7) | ((lane & 16) >> 1))) * AP + (lane & 8)) * 2);

    float acc[MT][NT][4] = {};

    auto load_tiles = [&](int k0, int buf) {
        #pragma unroll
        for (int t = 0; t < ACH; t++) {
            int c = tid + t * 256;
            int row = c >> 2, off = (c & 3) * 8;
            cpa16(sA0 + buf * (BM * AP * 2) + (row * AP + off) * 2,
                  A + (long)(i0 + row) * lda + k0 + off);
        }
        #pragma unroll
        for (int t = 0; t < BCH; t++) {
            int c = tid + t * 256;
            int row = c >> 2, off = (c & 3) * 8;
            cpa16(sB0 + buf * (BN * AP * 2) + (row * AP + off) * 2,
                  Bm + (long)(j0 + row) * ldb + k0 + off);
        }
        cpa_commit();
    };

    load_tiles(0, 0);
    cpa_wait0();
    __syncthreads();

    int KB = K / BK;
    for (int kb = 0; kb < KB; kb++) {
        int cur = kb & 1;
        if (kb + 1 < KB) load_tiles((kb + 1) * BK, cur ^ 1);
        uint32_t aB = aBase + cur * (BM * AP * 2);
        uint32_t bB = bBase + cur * (BN * AP * 2);
        uint32_t af[2][MT][4];
        uint32_t bf[2][NT][2];
        #pragma unroll
        for (int ks2 = 0; ks2 < 2; ks2++) {
            #pragma unroll
            for (int mt = 0; mt < MT; mt++)
                ldsm4(af[ks2][mt], aB + (mt * 16 * AP + ks2 * 16) * 2);
            #pragma unroll
            for (int p = 0; p < NT / 2; p++) {
                uint32_t r[4];
                ldsm4(r, bB + (p * 16 * AP + ks2 * 16) * 2);
                bf[ks2][2*p][0] = r[0]; bf[ks2][2*p][1] = r[1];
                bf[ks2][2*p+1][0] = r[2]; bf[ks2][2*p+1][1] = r[3];
            }
        }
        #pragma unroll
        for (int ks2 = 0; ks2 < 2; ks2++)
            #pragma unroll
            for (int mt = 0; mt < MT; mt++)
                #pragma unroll
                for (int nt = 0; nt < NT; nt++)
                    mma16816(acc[mt][nt], af[ks2][mt], bf[ks2][nt]);
        if (kb + 1 < KB) cpa_wait0();
        __syncthreads();
    }

    float* Cf = reinterpret_cast<float*>(Cv);
    __nv_bfloat16* Ch = reinterpret_cast<__nv_bfloat16*>(Cv);

    if (OUT_MODE == 3) {
        constexpr int SP = 33;
        float* stage = reinterpret_cast<float*>(&As[0][0][0]);
        int bb = i0 >> 10;
        int nbase = i0 & (NTOK - 1);
        #pragma unroll
        for (int pass = 0; pass < 4; pass++) {
            __syncthreads();
            int rlo = pass * 32;
            #pragma unroll
            for (int mt = 0; mt < MT; mt++) {
                #pragma unroll
                for (int h = 0; h < 2; h++) {
                    int il = m_w + mt*16 + g + 8*h;
                    if (il >= rlo && il < rlo + 32) {
                        #pragma unroll
                        for (int nt = 0; nt < NT; nt++) {
                            int j = n_w + nt*8 + tg*2;
                            float v0 = alpha * acc[mt][nt][2*h]   + bias[j0 + j];
                            float v1 = alpha * acc[mt][nt][2*h+1] + bias[j0 + j + 1];
                            const float* rp = &Res[(long)(i0 + il) * ldr + j0 + j];
                            v0 += rp[0]; v1 += rp[1];
                            stage[j * SP + (il & 31)]       = v0;
                            stage[(j + 1) * SP + (il & 31)] = v1;
                        }
                    }
                }
            }
            __syncthreads();
            for (int q = tid; q < BN * 2; q += 256) {
                int c = q >> 1, half = q & 1;
                float* op = &Cf[((long)bb * DIM + j0 + c) * NTOK + nbase + rlo + half*16];
                float* sp = &stage[c * SP + half * 16];
                #pragma unroll
                for (int s = 0; s < 4; s++) {
                    ((float4*)op)[s] = make_float4(sp[s*4], sp[s*4+1], sp[s*4+2], sp[s*4+3]);
                }
            }
        }
        return;
    }

    #pragma unroll
    for (int mt = 0; mt < MT; mt++) {
        #pragma unroll
        for (int h = 0; h < 2; h++) {
            int i = i0 + m_w + mt*16 + g + 8*h;
            #pragma unroll
            for (int nt = 0; nt < NT; nt++) {
                int j = j0 + n_w + nt*8 + tg*2;
                float v0 = alpha * acc[mt][nt][2*h+0];
                float v1 = alpha * acc[mt][nt][2*h+1];
                if (bias) { v0 += bias[j]; v1 += bias[j+1]; }
                if (OUT_MODE == 2) {
                    Ch[(long)i * ldc + (j >> 1)] = __float2bfloat16_rn(v0 * gelu_exact(v1));
                } else if (OUT_MODE == 1) {
                    *reinterpret_cast<__nv_bfloat162*>(&Ch[(long)i * ldc + j]) =
                        __floats2bfloat162_rn(v0, v1);
                } else {
                    if (Res) {
                        const float* rp = &Res[(long)i * ldr + j];
                        v0 += rp[0]; v1 += rp[1];
                    }
                    *reinterpret_cast<float2*>(&Cf[(long)i * ldc + j]) = make_float2(v0, v1);
                }
            }
        }
    }
}

// ---------------- fused flash attention (cp.async K/V pipeline) ---------------
#define FPITCH 72
#define FTILEB (64 * FPITCH * 2)
__global__ __launch_bounds__(128) void flash_kernel(
    const __nv_bfloat16* __restrict__ Q, int q_ld,
    const __nv_bfloat16* __restrict__ K,
    const __nv_bfloat16* __restrict__ V, int kv_ld,
    __nv_bfloat16* __restrict__ O,
    int nk, long kv_bstride)
{
    __shared__ __align__(16) __nv_bfloat16 Qs[64][FPITCH];
    __shared__ __align__(16) __nv_bfloat16 Ks[2][64][FPITCH];
    __shared__ __align__(16) __nv_bfloat16 Vs[2][64][FPITCH];
    uint32_t sQ = (uint32_t)__cvta_generic_to_shared(&Qs[0][0]);
    uint32_t sK = (uint32_t)__cvta_generic_to_shared(&Ks[0][0][0]);
    uint32_t sV = (uint32_t)__cvta_generic_to_shared(&Vs[0][0][0]);

    int tid = threadIdx.x, warp = tid >> 5, lane = tid & 31;
    int g = lane >> 2, tg = lane & 3;
    int b = blockIdx.y / HEADS, h = blockIdx.y % HEADS;
    const __nv_bfloat16* qb = Q + ((long)b*NTOK + blockIdx.x*64)*q_ld + h*DHEAD;
    const __nv_bfloat16* kb = K + (long)b*kv_bstride + h*DHEAD;
    const __nv_bfloat16* vb = V + (long)b*kv_bstride + h*DHEAD;
    __nv_bfloat16* ob = O + ((long)b*NTOK + blockIdx.x*64)*INNER + h*DHEAD;

    int mrow = warp * 16;
    uint32_t qBase = sQ + (uint32_t)(((mrow + (lane & 15)) * FPITCH + (lane >> 4) * 8) * 2);
    uint32_t kBase = sK + (uint32_t)((((lane & 7) | ((lane & 16) >> 1)) * FPITCH + (lane & 8)) * 2);
    uint32_t vBase = sV + (uint32_t)(((((lane >> 3) & 1) * 8 + (lane & 7)) * FPITCH + (lane >> 4) * 8) * 2);

    auto pf = [&](int kt, int buf) {
        #pragma unroll
        for (int t = 0; t < 4; t++) {
            int c = tid + t*128;
            int r = c >> 3, c8 = (c & 7) * 8;
            cpa16(sK + buf*FTILEB + (r*FPITCH + c8)*2, kb + (long)(kt + r)*kv_ld + c8);
            cpa16(sV + buf*FTILEB + (r*FPITCH + c8)*2, vb + (long)(kt + r)*kv_ld + c8);
        }
        cpa_commit();
    };

    #pragma unroll
    for (int t = 0; t < 4; t++) {
        int c = tid + t*128;
        int r = c >> 3, c8 = (c & 7) * 8;
        *reinterpret_cast<uint4*>(&Qs[r][c8]) =
            *reinterpret_cast<const uint4*>(&qb[(long)r*q_ld + c8]);
    }
    pf(0, 0);
    if (nk > 64) pf(64, 1);

    float m_i[2] = {-1e30f, -1e30f}, l_i[2] = {0.f, 0.f};
    float oa[8][4];
    #pragma unroll
    for (int nt = 0; nt < 8; nt++) { oa[nt][0]=0.f; oa[nt][1]=0.f; oa[nt][2]=0.f; oa[nt][3]=0.f; }

    __syncthreads();

    uint32_t qf[4][4];
    #pragma unroll
    for (int kc = 0; kc < 4; kc++)
        ldsm4(qf[kc], qBase + kc * 16 * 2);

    int T = nk >> 6;
    for (int t = 0; t < T; t++) {
        int buf = t & 1;
        if (t + 1 < T) cpa_wait1(); else cpa_wait0();
        __syncthreads();
        uint32_t kB = kBase + buf*FTILEB;
        uint32_t vB = vBase + buf*FTILEB;

        float s[8][4] = {};
        #pragma unroll
        for (int kc = 0; kc < 4; kc++) {
            uint32_t bk[8][2];
            #pragma unroll
            for (int p = 0; p < 4; p++) {
                uint32_t r[4];
                ldsm4(r, kB + (p * 16 * FPITCH + kc * 16) * 2);
                bk[2*p][0] = r[0]; bk[2*p][1] = r[1];
                bk[2*p+1][0] = r[2]; bk[2*p+1][1] = r[3];
            }
            #pragma unroll
            for (int nt = 0; nt < 8; nt++)
                mma16816(s[nt], qf[kc], bk[nt]);
        }

        #pragma unroll
        for (int h2 = 0; h2 < 2; h2++) {
            float mt = -1e30f;
            #pragma unroll
            for (int nt = 0; nt < 8; nt++)
                mt = fmaxf(mt, fmaxf(s[nt][2*h2], s[nt][2*h2+1]));
            mt = fmaxf(mt, __shfl_xor_sync(0xffffffffu, mt, 1));
            mt = fmaxf(mt, __shfl_xor_sync(0xffffffffu, mt, 2));
            float mnew = fmaxf(m_i[h2], mt);
            float corr = __expf(m_i[h2] - mnew);
            m_i[h2] = mnew;
            float lsum = 0.f;
            #pragma unroll
            for (int nt = 0; nt < 8; nt++) {
                float e0 = __expf(s[nt][2*h2]   - mnew);
                float e1 = __expf(s[nt][2*h2+1] - mnew);
                s[nt][2*h2] = e0; s[nt][2*h2+1] = e1;
                lsum += e0 + e1;
            }
            lsum += __shfl_xor_sync(0xffffffffu, lsum, 1);
            lsum += __shfl_xor_sync(0xffffffffu, lsum, 2);
            l_i[h2] = l_i[h2] * corr + lsum;
            #pragma unroll
            for (int nt = 0; nt < 8; nt++) { oa[nt][2*h2] *= corr; oa[nt][2*h2+1] *= corr; }
        }

        #pragma unroll
        for (int kc = 0; kc < 4; kc++) {
            uint32_t ap[4];
            __nv_bfloat162 t0 = __floats2bfloat162_rn(s[2*kc][0],   s[2*kc][1]);
            __nv_bfloat162 t1 = __floats2bfloat162_rn(s[2*kc][2],   s[2*kc][3]);
            __nv_bfloat162 t2 = __floats2bfloat162_rn(s[2*kc+1][0], s[2*kc+1][1]);
            __nv_bfloat162 t3 = __floats2bfloat162_rn(s[2*kc+1][2], s[2*kc+1][3]);
            ap[0] = *reinterpret_cast<uint32_t*>(&t0);
            ap[1] = *reinterpret_cast<uint32_t*>(&t1);
            ap[2] = *reinterpret_cast<uint32_t*>(&t2);
            ap[3] = *reinterpret_cast<uint32_t*>(&t3);
            uint32_t bv[8][2];
            #pragma unroll
            for (int p = 0; p < 4; p++) {
                uint32_t r[4];
                ldsm4t(r, vB + (kc * 16 * FPITCH + p * 16) * 2);
                bv[2*p][0] = r[0]; bv[2*p][1] = r[1];
                bv[2*p+1][0] = r[2]; bv[2*p+1][1] = r[3];
            }
            #pragma unroll
            for (int nt = 0; nt < 8; nt++)
                mma16816(oa[nt], ap, bv[nt]);
        }
        __syncthreads();
        if (t + 2 < T) pf((t + 2) * 64, buf);
    }

    #pragma unroll
    for (int h2 = 0; h2 < 2; h2++) {
        float inv = 1.f / l_i[h2];
        int r = mrow + g + 8*h2;
        #pragma unroll
        for (int nt = 0; nt < 8; nt++) {
            *reinterpret_cast<__nv_bfloat162*>(&ob[(long)r*INNER + nt*8 + tg*2]) =
                __floats2bfloat162_rn(oa[nt][2*h2] * inv, oa[nt][2*h2+1] * inv);
        }
    }
}

// ---------------- fused weight conversion -------------------------------------
#define SQW (INNER*DIM)
#define N_CONV  (DIM*DIM)
#define N_WF1   (2*DFF*DIM)
#define N_WF2   (DIM*DFF)
#define TOT_W   (N_CONV + 3*SQW + SQW + SQW + 2*SQW + SQW + N_WF1 + N_WF2)
__global__ void convert_all_kernel(
    const float* __restrict__ conv_w,
    const float* __restrict__ a1q, const float* __restrict__ a1k,
    const float* __restrict__ a1v, const float* __restrict__ a1o,
    const float* __restrict__ a2q, const float* __restrict__ a2k,
    const float* __restrict__ a2v, const float* __restrict__ a2o,
    const float* __restrict__ f1,  const float* __restrict__ f2,
    const float* __restrict__ b1)
{
    long i = (long)(blockIdx.x * 256 + threadIdx.x) * 4;
    auto cvt = [](const float* s, __nv_bfloat16* d, long si, long di, float sc) {
        float4 v = *reinterpret_cast<const float4*>(s + si);
        *reinterpret_cast<__nv_bfloat162*>(d + di)     = __floats2bfloat162_rn(v.x*sc, v.y*sc);
        *reinterpret_cast<__nv_bfloat162*>(d + di + 2) = __floats2bfloat162_rn(v.z*sc, v.w*sc);
    };
    if (i < N_CONV) { cvt(conv_w, g_wconv, i, i, 1.f); return; }
    i -= N_CONV;
    if (i < SQW)    { cvt(a1q, g_wqkv, i, i, 0.125f); return; }
    i -= SQW;
    if (i < SQW)    { cvt(a1k, g_wqkv, i, i + SQW, 1.f); return; }
    i -= SQW;
    if (i < SQW)    { cvt(a1v, g_wqkv, i, i + 2*SQW, 1.f); return; }
    i -= SQW;
    if (i < SQW)    { cvt(a1o, g_w1o, i, i, 1.f); return; }
    i -= SQW;
    if (i < SQW)    { cvt(a2q, g_w2q, i, i, 0.125f); return; }
    i -= SQW;
    if (i < SQW)    { cvt(a2k, g_wkv2, i, i, 1.f); return; }
    i -= SQW;
    if (i < SQW)    { cvt(a2v, g_wkv2, i, i + SQW, 1.f); return; }
    i -= SQW;
    if (i < SQW)    { cvt(a2o, g_w2o, i, i, 1.f); return; }
    i -= SQW;
    if (i < N_WF1) {
        int row = (int)(i / DIM), col = (int)(i % DIM);
        int srow = (row >> 1) + (row & 1) * DFF;
        cvt(f1, g_wf1p, (long)srow * DIM + col, i, 1.f);
        return;
    }
    i -= N_WF1;
    if (i < N_WF2)  { cvt(f2, g_wf2, i, i, 1.f); return; }
    i -= N_WF2;
    if (i < 2*DFF) {
        #pragma unroll
        for (int s = 0; s < 4; s++) {
            long o = i + s;
            g_pb1[o] = b1[(o >> 1) + (o & 1) * DFF];
        }
    }
}

// ---------------- small kernels ----------------------------------------------
__global__ __launch_bounds__(256) void emb_kernel(
    const float* __restrict__ emb,
    const float* __restrict__ w,
    const float* __restrict__ bias)
{
    int b = blockIdx.x >> 4, chunk = blockIdx.x & 15;
    __shared__ float e[EMBD];
    int tid = threadIdx.x, warp = tid >> 5, lane = tid & 31;
    if (tid < EMBD) {
        float v = emb[b * EMBD + tid];
        e[tid] = v / (1.f + __expf(-v));
    }
    __syncthreads();
    float4 ev = reinterpret_cast<const float4*>(e)[lane];
    #pragma unroll
    for (int q = 0; q < 8; q++) {
        int o = chunk * 64 + warp * 8 + q;     // 0..1023
        float4 wv = reinterpret_cast<const float4*>(w + (long)o * EMBD)[lane];
        float p = wv.x*ev.x + wv.y*ev.y + wv.z*ev.z + wv.w*ev.w;
        #pragma unroll
        for (int s = 16; s > 0; s >>= 1) p += __shfl_xor_sync(0xffffffffu, p, s);
        if (lane == 0) {
            float acc = p + bias[o];
            if (o < DIM) g_scale[b * DIM + o] = 1.f + acc;
            else         g_shift[b * DIM + (o - DIM)] = acc;
        }
    }
}

__global__ void gn_stats_kernel(const float* __restrict__ X)
{
    __shared__ float sh[32];
    int b = blockIdx.x / GROUPS, g = blockIdx.x % GROUPS;
    const int CH = DIM / GROUPS;
    const float* p = X + ((long)b * DIM + (long)g * CH) * NTOK;
    float s = 0.f, ss = 0.f;
    for (int i = threadIdx.x; i < CH * NTOK / 4; i += blockDim.x) {
        float4 v = reinterpret_cast<const float4*>(p)[i];
        s  += v.x + v.y + v.z + v.w;
        ss += v.x*v.x + v.y*v.y + v.z*v.z + v.w*v.w;
    }
    s  = block_reduce_sum(s, sh);
    ss = block_reduce_sum(ss, sh);
    if (threadIdx.x == 0) {
        float inv = 1.f / (CH * NTOK);
        float mu = s * inv;
        float var = ss * inv - mu * mu;
        g_gn_mu[blockIdx.x] = mu;
        g_gn_rs[blockIdx.x] = rsqrtf(var + 1e-6f);
    }
}

__global__ void gn_apply_t_kernel(const float* __restrict__ X,
                                  const float* __restrict__ gn_g,
                                  const float* __restrict__ gn_b,
                                  __nv_bfloat16* __restrict__ HT,
                                  float* __restrict__ XT)
{
    __shared__ float tile[32][33];
    int b = blockIdx.z;
    int n0 = blockIdx.x * 32, c0 = blockIdx.y * 32;
    for (int r = threadIdx.y; r < 32; r += 8)
        tile[r][threadIdx.x] = X[((long)b * DIM + c0 + r) * NTOK + n0 + threadIdx.x];
    __syncthreads();
    int c = c0 + threadIdx.x;
    int grp = b * GROUPS + (c >> 4);
    float mu = g_gn_mu[grp], rs = g_gn_rs[grp];
    float gg = gn_g[c], bb = gn_b[c];
    float sc = g_scale[b * DIM + c], sf = g_shift[b * DIM + c];
    for (int r = threadIdx.y; r < 32; r += 8) {
        int n = n0 + r;
        float raw = tile[threadIdx.x][r];
        float v = (raw - mu) * rs * gg + bb;
        v = v * sc + sf;
        float s = v / (1.f + __expf(-v));
        HT[((long)b * NTOK + n) * DIM + c] = __float2bfloat16_rn(s);
        XT[((long)b * NTOK + n) * DIM + c] = raw;
    }
}

__global__ void ctx_transpose_kernel(const float* __restrict__ CTX,
                                     __nv_bfloat16* __restrict__ CT)
{
    __shared__ float tile[32][33];
    int b = blockIdx.z;
    int m0 = blockIdx.x * 32, c0 = blockIdx.y * 32;
    for (int r = threadIdx.y; r < 32; r += 8)
        tile[r][threadIdx.x] = CTX[((long)b * CDIM + c0 + r) * MTOK + m0 + threadIdx.x];
    __syncthreads();
    for (int r = threadIdx.y; r < 32; r += 8)
        CT[((long)b * MTOK + m0 + r) * CDIM + c0 + threadIdx.x] =
            __float2bfloat16_rn(tile[threadIdx.x][r]);
}

__global__ void layernorm_kernel(const float* __restrict__ X, __nv_bfloat16* __restrict__ Y,
                                 const float* __restrict__ g, const float* __restrict__ b)
{
    __shared__ float sh[32];
    long t = blockIdx.x;
    const float* x = X + t * DIM;
    __nv_bfloat16* y = Y + t * DIM;
    float s = 0.f, ss = 0.f;
    for (int i = threadIdx.x; i < DIM; i += blockDim.x) {
        float v = x[i]; s += v; ss += v * v;
    }
    s  = block_reduce_sum(s, sh);
    ss = block_reduce_sum(ss, sh);
    float mu = s * (1.f / DIM);
    float var = ss * (1.f / DIM) - mu * mu;
    float rs = rsqrtf(var + 1e-5f);
    for (int i = threadIdx.x; i < DIM; i += blockDim.x)
        y[i] = __float2bfloat16_rn((x[i] - mu) * rs * g[i] + b[i]);
}

// ---------------- host orchestration (single stream) -------------------------
template<int OUT_MODE>
static void launch_bb(const __nv_bfloat16* A, int lda, const __nv_bfloat16* B, int ldb,
                      void* C, int ldc, const float* bias, const float* R, int ldr,
                      int M, int N, int K, float alpha)
{
    dim3 grid(N / 128, M / 128);
    gemm_bb<128,128,64,32,OUT_MODE><<<grid, 256>>>(A, lda, B, ldb, C, ldc,
                                                   bias, R, ldr, K, alpha);
}

extern "C" void kernel_launch(void* const* d_in, const int* in_sizes, int n_in,
                              void* d_out, int out_size)
{
    const float* x      = (const float*)d_in[0];
    const float* emb    = (const float*)d_in[1];
    const float* ctx    = (const float*)d_in[2];
    const float* w_emb  = (const float*)d_in[3];
    const float* b_emb  = (const float*)d_in[4];
    const float* gn_g   = (const float*)d_in[5];
    const float* gn_b   = (const float*)d_in[6];
    const float* conv_w = (const float*)d_in[7];
    const float* conv_b = (const float*)d_in[8];
    const float* a1_wq  = (const float*)d_in[9];
    const float* a1_wk  = (const float*)d_in[10];
    const float* a1_wv  = (const float*)d_in[11];
    const float* a1_wo  = (const float*)d_in[12];
    const float* a1_bo  = (const float*)d_in[13];
    const float* a2_wq  = (const float*)d_in[14];
    const float* a2_wk  = (const float*)d_in[15];
    const float* a2_wv  = (const float*)d_in[16];
    const float* a2_wo  = (const float*)d_in[17];
    const float* a2_bo  = (const float*)d_in[18];
    const float* ln1_g  = (const float*)d_in[19];
    const float* ln1_b  = (const float*)d_in[20];
    const float* ln2_g  = (const float*)d_in[21];
    const float* ln2_b  = (const float*)d_in[22];
    const float* ln3_g  = (const float*)d_in[23];
    const float* ln3_b  = (const float*)d_in[24];
    const float* ff_w1  = (const float*)d_in[25];
    const float* ff_b1  = (const float*)d_in[26];
    const float* ff_w2  = (const float*)d_in[27];
    const float* ff_b2  = (const float*)d_in[28];
    float* out = (float*)d_out;

    float *xt, *xT, *pb1;
    __nv_bfloat16 *bbuf, *qkvh, *qh, *kvh2, *oh, *vfh, *ctxT;
    __nv_bfloat16 *wconv, *wqkv, *w1o, *w2q, *wkv2, *w2o, *wf1p, *wf2;
    cudaGetSymbolAddress((void**)&xt,   g_xt);
    cudaGetSymbolAddress((void**)&xT,   g_buf);
    cudaGetSymbolAddress((void**)&pb1,  g_pb1);
    cudaGetSymbolAddress((void**)&bbuf, g_bbuf);
    cudaGetSymbolAddress((void**)&qkvh, g_qkvh);
    cudaGetSymbolAddress((void**)&qh,   g_qh);
    cudaGetSymbolAddress((void**)&kvh2, g_kvh2);
    cudaGetSymbolAddress((void**)&oh,   g_oh);
    cudaGetSymbolAddress((void**)&vfh,  g_vfh);
    cudaGetSymbolAddress((void**)&ctxT, g_ctxT);
    cudaGetSymbolAddress((void**)&wconv, g_wconv);
    cudaGetSymbolAddress((void**)&wqkv, g_wqkv);
    cudaGetSymbolAddress((void**)&w1o,  g_w1o);
    cudaGetSymbolAddress((void**)&w2q,  g_w2q);
    cudaGetSymbolAddress((void**)&wkv2, g_wkv2);
    cudaGetSymbolAddress((void**)&w2o,  g_w2o);
    cudaGetSymbolAddress((void**)&wf1p, g_wf1p);
    cudaGetSymbolAddress((void**)&wf2,  g_wf2);

    const int MTOT = BSZ * NTOK;

    // ---- prologue (single stream) ----
    {
        long tot4 = TOT_W / 4 + (2*DFF) / 4;
        int blocks = (int)((tot4 + 255) / 256);
        convert_all_kernel<<<blocks, 256>>>(conv_w, a1_wq, a1_wk, a1_wv, a1_wo,
                                            a2_wq, a2_wk, a2_wv, a2_wo,
                                            ff_w1, ff_w2, ff_b1);
    }
    ctx_transpose_kernel<<<dim3(MTOK/32, CDIM/32, BSZ), dim3(32, 8)>>>(ctx, ctxT);
    launch_bb<1>(ctxT, CDIM, wkv2, CDIM, kvh2, 2*INNER, nullptr, nullptr, 0,
                 BSZ*MTOK, 2*INNER, CDIM, 1.f);

    // ---- residual branch ----
    emb_kernel<<<BSZ * 16, 256>>>(emb, w_emb, b_emb);
    gn_stats_kernel<<<BSZ * GROUPS, 256>>>(x);
    gn_apply_t_kernel<<<dim3(NTOK/32, DIM/32, BSZ), dim3(32, 8)>>>(x, gn_g, gn_b, bbuf, xT);
    launch_bb<0>(bbuf, DIM, wconv, DIM, xt, DIM, conv_b, xT, DIM,
                 MTOT, DIM, DIM, 1.f);

    // ---- self attention ----
    layernorm_kernel<<<MTOT, 256>>>(xt, bbuf, ln1_g, ln1_b);
    launch_bb<1>(bbuf, DIM, wqkv, DIM, qkvh, 3*INNER, nullptr, nullptr, 0,
                 MTOT, 3*INNER, DIM, 1.f);
    flash_kernel<<<dim3(NTOK/64, BSZ*HEADS), 128>>>(
        qkvh, 3*INNER, qkvh + INNER, qkvh + 2*INNER, 3*INNER, oh,
        NTOK, (long)NTOK*3*INNER);
    launch_bb<0>(oh, INNER, w1o, INNER, xt, DIM, a1_bo, xt, DIM, MTOT, DIM, INNER, 1.f);

    // ---- cross attention ----
    layernorm_kernel<<<MTOT, 256>>>(xt, bbuf, ln2_g, ln2_b);
    launch_bb<1>(bbuf, DIM, w2q, DIM, qh, INNER, nullptr, nullptr, 0,
                 MTOT, INNER, DIM, 1.f);
    flash_kernel<<<dim3(NTOK/64, BSZ*HEADS), 128>>>(
        qh, INNER, kvh2, kvh2 + INNER, 2*INNER, oh,
        MTOK, (long)MTOK*2*INNER);
    launch_bb<0>(oh, INNER, w2o, INNER, xt, DIM, a2_bo, xt, DIM, MTOT, DIM, INNER, 1.f);

    // ---- GEGLU feed-forward ----
    layernorm_kernel<<<MTOT, 256>>>(xt, bbuf, ln3_g, ln3_b);
    launch_bb<2>(bbuf, DIM, wf1p, DIM, vfh, DFF, pb1, nullptr, 0,
                 MTOT, 2*DFF, DIM, 1.f);
    launch_bb<3>(vfh, DFF, wf2, DFF, out, 0, ff_b2, xt, DIM, MTOT, DIM, DFF, 1.f);
}